// round 3
// baseline (speedup 1.0000x reference)
#include <cuda_runtime.h>
#include <cstddef>

#define DD 512
#define NNODE 100000

// ---- static device scratch (allocation-free rule) ----
__device__ float g_h0[NNODE * DD];
__device__ float g_h1[NNODE * DD];
__device__ float g_o0[NNODE * DD];
__device__ float g_o1[NNODE * DD];
__device__ float g_agg[NNODE * DD];
__device__ float g_cnt[NNODE];
__device__ float g_Wp[8 * DD * DD];   // 8 precombined 512x512 weights
__device__ float g_bp[4 * DD];        // 4 precombined biases

// ---------------- elementwise leaky relu ----------------
__global__ void lrelu_k(const float4* __restrict__ in, float4* __restrict__ out, int n4) {
    int i = blockIdx.x * blockDim.x + threadIdx.x;
    if (i >= n4) return;
    float4 v = in[i];
    v.x = v.x > 0.f ? v.x : 0.01f * v.x;
    v.y = v.y > 0.f ? v.y : 0.01f * v.y;
    v.z = v.z > 0.f ? v.z : 0.01f * v.z;
    v.w = v.w > 0.f ? v.w : 0.01f * v.w;
    out[i] = v;
}

// ---------------- edge scatter-add (segment sum) ----------------
// one block (128 threads) per edge; each thread moves 4 floats
__global__ void scatter_k(const float* __restrict__ feat, const int* __restrict__ ei, int E,
                          float* __restrict__ agg, float* __restrict__ cnt) {
    int e = blockIdx.x;
    int s = ei[e];
    int d = ei[E + e];
    const float4* sp = (const float4*)(feat + (size_t)s * DD);
    float* dp = agg + (size_t)d * DD;
    int t = threadIdx.x;
    float4 v = sp[t];
    atomicAdd(dp + 4 * t + 0, v.x);
    atomicAdd(dp + 4 * t + 1, v.y);
    atomicAdd(dp + 4 * t + 2, v.z);
    atomicAdd(dp + 4 * t + 3, v.w);
    if (t == 0) atomicAdd(cnt + d, 1.0f);
}

// ---------------- divide rows by counts (mean) ----------------
__global__ void divide_k(float4* __restrict__ agg, const float* __restrict__ cnt, int n4) {
    int i = blockIdx.x * blockDim.x + threadIdx.x;
    if (i >= n4) return;
    int row = i >> 7;  // 128 float4 per 512-float row
    float s = 1.0f / fmaxf(cnt[row], 1.0f);
    float4 v = agg[i];
    v.x *= s; v.y *= s; v.z *= s; v.w *= s;
    agg[i] = v;
}

// ---------------- bias precombination: b' = bn@WuT + bs@WuB + bu ----------------
__global__ void biascomb_k(const float* __restrict__ bn, const float* __restrict__ bs,
                           const float* __restrict__ bu, const float* __restrict__ Wu,
                           float* __restrict__ bp) {
    int j = blockIdx.x * blockDim.x + threadIdx.x;
    if (j >= DD) return;
    const float* WuT = Wu;
    const float* WuB = Wu + DD * DD;
    float acc = bu[j];
    for (int k = 0; k < DD; k++)
        acc += bn[k] * WuT[k * DD + j] + bs[k] * WuB[k * DD + j];
    bp[j] = acc;
}

// ---------------- fused dual GEMM: C = A@Wa (+ B@Wb) (+ bias) ----------------
// Fixed K = N = 512, row-major everywhere. 128x128 block tile, 8x8 per thread.
__global__ __launch_bounds__(256, 2) void gemm_dual_k(
    const float* __restrict__ A, const float* __restrict__ Wa,
    const float* __restrict__ B, const float* __restrict__ Wb,
    const float* __restrict__ bias, float* __restrict__ C, int M) {
    __shared__ float As[16][128];   // transposed A tile: As[k][m]
    __shared__ float Bs[16][128];   // weight tile: Bs[k][n]

    const int tid = threadIdx.x;
    const int tx = tid & 15;        // 0..15 -> 8 output cols each
    const int ty = tid >> 4;        // 0..15 -> 8 output rows each
    const int row0 = blockIdx.y * 128;
    const int col0 = blockIdx.x * 128;

    float acc[8][8];
#pragma unroll
    for (int i = 0; i < 8; i++)
#pragma unroll
        for (int j = 0; j < 8; j++) acc[i][j] = 0.f;

    // A-tile loader mapping: thread covers row lm, k-slice lk..lk+7
    const int lm = tid >> 1;
    const int lk = (tid & 1) * 8;
    // W-tile loader mapping: thread covers k-row wk, cols wc..wc+7
    const int wk = tid >> 4;
    const int wc = (tid & 15) * 8;

    const int nPh = (B != nullptr) ? 2 : 1;
    for (int ph = 0; ph < nPh; ph++) {
        const float* Ap = ph ? B : A;
        const float* Wp = ph ? Wb : Wa;
        for (int kk = 0; kk < 512; kk += 16) {
            float4 a0, a1;
            int grow = row0 + lm;
            if (grow < M) {
                const float* p = Ap + (size_t)grow * 512 + kk + lk;
                a0 = *(const float4*)p;
                a1 = *(const float4*)(p + 4);
            } else {
                a0 = make_float4(0.f, 0.f, 0.f, 0.f);
                a1 = a0;
            }
            const float* wp = Wp + (size_t)(kk + wk) * 512 + col0 + wc;
            float4 w0 = *(const float4*)wp;
            float4 w1 = *(const float4*)(wp + 4);

            As[lk + 0][lm] = a0.x; As[lk + 1][lm] = a0.y;
            As[lk + 2][lm] = a0.z; As[lk + 3][lm] = a0.w;
            As[lk + 4][lm] = a1.x; As[lk + 5][lm] = a1.y;
            As[lk + 6][lm] = a1.z; As[lk + 7][lm] = a1.w;
            *(float4*)&Bs[wk][wc] = w0;
            *(float4*)&Bs[wk][wc + 4] = w1;
            __syncthreads();

#pragma unroll
            for (int k = 0; k < 16; k++) {
                float ra[8], rb[8];
                *(float4*)&ra[0] = *(const float4*)&As[k][ty * 8];
                *(float4*)&ra[4] = *(const float4*)&As[k][ty * 8 + 4];
                *(float4*)&rb[0] = *(const float4*)&Bs[k][tx * 8];
                *(float4*)&rb[4] = *(const float4*)&Bs[k][tx * 8 + 4];
#pragma unroll
                for (int i = 0; i < 8; i++)
#pragma unroll
                    for (int j = 0; j < 8; j++)
                        acc[i][j] += ra[i] * rb[j];
            }
            __syncthreads();
        }
    }

    float bl[8];
    if (bias != nullptr) {
        *(float4*)&bl[0] = *(const float4*)(bias + col0 + tx * 8);
        *(float4*)&bl[4] = *(const float4*)(bias + col0 + tx * 8 + 4);
    } else {
#pragma unroll
        for (int j = 0; j < 8; j++) bl[j] = 0.f;
    }

#pragma unroll
    for (int i = 0; i < 8; i++) {
        int r = row0 + ty * 8 + i;
        if (r >= M) break;
        float* cp = C + (size_t)r * 512 + col0 + tx * 8;
        float4 o0 = make_float4(acc[i][0] + bl[0], acc[i][1] + bl[1],
                                acc[i][2] + bl[2], acc[i][3] + bl[3]);
        float4 o1 = make_float4(acc[i][4] + bl[4], acc[i][5] + bl[5],
                                acc[i][6] + bl[6], acc[i][7] + bl[7]);
        *(float4*)cp = o0;
        *(float4*)(cp + 4) = o1;
    }
}

// ---------------- host-side SAGE step ----------------
static void run_sage(const float* hsrc, const float* hdst, const int* ei, int E, int n_dst,
                     const float* Wpn, const float* Wps, const float* bp, float* out,
                     float* agg, float* cnt) {
    cudaMemsetAsync(agg, 0, (size_t)n_dst * DD * sizeof(float));
    cudaMemsetAsync(cnt, 0, (size_t)n_dst * sizeof(float));
    scatter_k<<<E, 128>>>(hsrc, ei, E, agg, cnt);
    int n4 = n_dst * (DD / 4);
    divide_k<<<(n4 + 255) / 256, 256>>>((float4*)agg, cnt, n4);
    dim3 g(4, (n_dst + 127) / 128);
    gemm_dual_k<<<g, 256>>>(agg, Wpn, hdst, Wps, bp, out, n_dst);
}

extern "C" void kernel_launch(void* const* d_in, const int* in_sizes, int n_in,
                              void* d_out, int out_size) {
    const float* x0 = (const float*)d_in[0];
    const float* x1 = (const float*)d_in[1];
    const int* ei01 = (const int*)d_in[2];
    const int* ei10 = (const int*)d_in[3];
    const int N0 = in_sizes[0] / DD;
    const int N1 = in_sizes[1] / DD;
    const int E01 = in_sizes[2] / 2;
    const int E10 = in_sizes[3] / 2;

    float *h0, *h1, *o0, *o1, *agg, *cnt, *Wp, *bp;
    cudaGetSymbolAddress((void**)&h0, g_h0);
    cudaGetSymbolAddress((void**)&h1, g_h1);
    cudaGetSymbolAddress((void**)&o0, g_o0);
    cudaGetSymbolAddress((void**)&o1, g_o1);
    cudaGetSymbolAddress((void**)&agg, g_agg);
    cudaGetSymbolAddress((void**)&cnt, g_cnt);
    cudaGetSymbolAddress((void**)&Wp, g_Wp);
    cudaGetSymbolAddress((void**)&bp, g_bp);

    // ---- precombine weights: Wp[2s] = Wn@WuT, Wp[2s+1] = Ws@WuB, bp[s] ----
    for (int s = 0; s < 4; s++) {
        const float* Wn  = (const float*)d_in[4 + 6 * s + 0];
        const float* bn  = (const float*)d_in[4 + 6 * s + 1];
        const float* Ws_ = (const float*)d_in[4 + 6 * s + 2];
        const float* bs  = (const float*)d_in[4 + 6 * s + 3];
        const float* Wu  = (const float*)d_in[4 + 6 * s + 4];
        const float* bu  = (const float*)d_in[4 + 6 * s + 5];
        dim3 gw(4, 4);
        gemm_dual_k<<<gw, 256>>>(Wn, Wu, nullptr, nullptr, nullptr,
                                 Wp + (size_t)(2 * s) * DD * DD, DD);
        gemm_dual_k<<<gw, 256>>>(Ws_, Wu + DD * DD, nullptr, nullptr, nullptr,
                                 Wp + (size_t)(2 * s + 1) * DD * DD, DD);
        biascomb_k<<<2, 256>>>(bn, bs, bu, Wu, bp + s * DD);
    }

    const int n40 = N0 * (DD / 4);
    const int n41 = N1 * (DD / 4);

    // ---- layer 1 ----
    lrelu_k<<<(n40 + 255) / 256, 256>>>((const float4*)x0, (float4*)h0, n40);
    lrelu_k<<<(n41 + 255) / 256, 256>>>((const float4*)x1, (float4*)h1, n41);
    // l1_01: src h0 -> dst nodes of type 1
    run_sage(h0, h1, ei01, E01, N1,
             Wp + (size_t)0 * DD * DD, Wp + (size_t)1 * DD * DD, bp + 0 * DD, o1, agg, cnt);
    // l1_10: src h1 -> dst nodes of type 0
    run_sage(h1, h0, ei10, E10, N0,
             Wp + (size_t)2 * DD * DD, Wp + (size_t)3 * DD * DD, bp + 1 * DD, o0, agg, cnt);

    // ---- layer 2 ----
    lrelu_k<<<(n40 + 255) / 256, 256>>>((const float4*)o0, (float4*)h0, n40);
    lrelu_k<<<(n41 + 255) / 256, 256>>>((const float4*)o1, (float4*)h1, n41);

    float* out0 = (float*)d_out;                 // final o0
    float* out1 = out0 + (size_t)N0 * DD;        // final o1
    // l2_01 -> o1 (dst type 1)
    run_sage(h0, h1, ei01, E01, N1,
             Wp + (size_t)4 * DD * DD, Wp + (size_t)5 * DD * DD, bp + 2 * DD, out1, agg, cnt);
    // l2_10 -> o0 (dst type 0)
    run_sage(h1, h0, ei10, E10, N0,
             Wp + (size_t)6 * DD * DD, Wp + (size_t)7 * DD * DD, bp + 3 * DD, out0, agg, cnt);
}

// round 4
// speedup vs baseline: 2.7338x; 2.7338x over previous
#include <cuda_runtime.h>
#include <cuda_bf16.h>
#include <cstdint>
#include <cstddef>

#define DD 512
#define NNODE 100000
#define EMAX 1000000
typedef __nv_bfloat16 bf16;

// ---- static device scratch (allocation-free rule) ----
__device__ float g_h0[NNODE * DD];
__device__ float g_h1[NNODE * DD];
__device__ float g_o0[NNODE * DD];
__device__ float g_o1[NNODE * DD];
__device__ bf16  g_h0h[NNODE * DD];
__device__ bf16  g_h0l[NNODE * DD];
__device__ bf16  g_h1h[NNODE * DD];
__device__ bf16  g_h1l[NNODE * DD];
__device__ bf16  g_aggh[NNODE * DD];
__device__ bf16  g_aggl[NNODE * DD];
__device__ float g_Wp[8 * DD * DD];
__device__ bf16  g_Wph[8 * DD * DD];
__device__ bf16  g_Wpl[8 * DD * DD];
__device__ float g_bp[4 * DD];
__device__ int   g_csr01[EMAX];
__device__ int   g_csr10[EMAX];
__device__ int   g_rs01[NNODE + 1];
__device__ int   g_rs10[NNODE + 1];
__device__ int   g_cnt[NNODE];
__device__ int   g_part[NNODE];
__device__ int   g_bsum[256];
__device__ int   g_cur[NNODE];

// ================= helpers =================
__device__ __forceinline__ void split4(float4 v, uint2& h, uint2& l) {
    bf16 hx = __float2bfloat16(v.x), hy = __float2bfloat16(v.y);
    bf16 hz = __float2bfloat16(v.z), hw = __float2bfloat16(v.w);
    bf16 lx = __float2bfloat16(v.x - __bfloat162float(hx));
    bf16 ly = __float2bfloat16(v.y - __bfloat162float(hy));
    bf16 lz = __float2bfloat16(v.z - __bfloat162float(hz));
    bf16 lw = __float2bfloat16(v.w - __bfloat162float(hw));
    h.x = ((uint32_t)__bfloat16_as_ushort(hy) << 16) | __bfloat16_as_ushort(hx);
    h.y = ((uint32_t)__bfloat16_as_ushort(hw) << 16) | __bfloat16_as_ushort(hz);
    l.x = ((uint32_t)__bfloat16_as_ushort(ly) << 16) | __bfloat16_as_ushort(lx);
    l.y = ((uint32_t)__bfloat16_as_ushort(lw) << 16) | __bfloat16_as_ushort(lz);
}

// ================= elementwise: lrelu + fp32 + bf16 split =================
__global__ void hfuse_k(const float4* __restrict__ in, float4* __restrict__ f,
                        uint2* __restrict__ hi, uint2* __restrict__ lo, int n4) {
    int i = blockIdx.x * blockDim.x + threadIdx.x;
    if (i >= n4) return;
    float4 v = in[i];
    v.x = v.x > 0.f ? v.x : 0.01f * v.x;
    v.y = v.y > 0.f ? v.y : 0.01f * v.y;
    v.z = v.z > 0.f ? v.z : 0.01f * v.z;
    v.w = v.w > 0.f ? v.w : 0.01f * v.w;
    f[i] = v;
    uint2 h, l;
    split4(v, h, l);
    hi[i] = h; lo[i] = l;
}

// weight fp32 -> bf16 hi/lo
__global__ void wconv_k(const float4* __restrict__ in, uint2* __restrict__ hi,
                        uint2* __restrict__ lo, int n4) {
    int i = blockIdx.x * blockDim.x + threadIdx.x;
    if (i >= n4) return;
    uint2 h, l;
    split4(in[i], h, l);
    hi[i] = h; lo[i] = l;
}

// ================= CSR build =================
__global__ void hist_k(const int* __restrict__ ei, int E, int* __restrict__ cnt) {
    int e = blockIdx.x * blockDim.x + threadIdx.x;
    if (e < E) atomicAdd(&cnt[ei[E + e]], 1);
}

__global__ void scan1_k(const int* __restrict__ cnt, int N, int* __restrict__ part,
                        int* __restrict__ bsum) {
    __shared__ int sh[1024];
    int t = threadIdx.x;
    int i = blockIdx.x * 1024 + t;
    sh[t] = (i < N) ? cnt[i] : 0;
    __syncthreads();
    for (int off = 1; off < 1024; off <<= 1) {
        int v = (t >= off) ? sh[t - off] : 0;
        __syncthreads();
        sh[t] += v;
        __syncthreads();
    }
    if (i < N) part[i] = sh[t];
    if (t == 1023) bsum[blockIdx.x] = sh[1023];
}

__global__ void scan2_k(int* __restrict__ bsum, int nb) {
    __shared__ int sh[128];
    int t = threadIdx.x;
    sh[t] = (t < nb) ? bsum[t] : 0;
    __syncthreads();
    for (int off = 1; off < 128; off <<= 1) {
        int v = (t >= off) ? sh[t - off] : 0;
        __syncthreads();
        sh[t] += v;
        __syncthreads();
    }
    if (t < nb) bsum[t] = sh[t];
}

__global__ void scan3_k(const int* __restrict__ part, const int* __restrict__ bsum,
                        int* __restrict__ rs, int N) {
    int i = blockIdx.x * blockDim.x + threadIdx.x;
    if (i < N) {
        int b = i >> 10;
        int off = (b > 0) ? bsum[b - 1] : 0;
        rs[i + 1] = part[i] + off;
    }
    if (i == 0) rs[0] = 0;
}

__global__ void fill_k(const int* __restrict__ ei, int E, const int* __restrict__ rs,
                       int* __restrict__ cur, int* __restrict__ csr) {
    int e = blockIdx.x * blockDim.x + threadIdx.x;
    if (e >= E) return;
    int s = ei[e], d = ei[E + e];
    int pos = atomicAdd(&cur[d], 1);
    csr[rs[d] + pos] = s;
}

// ================= CSR gather (mean) -> bf16 hi/lo =================
__global__ void gather_k(const float* __restrict__ feat, const int* __restrict__ csr,
                         const int* __restrict__ rs, int N,
                         uint2* __restrict__ aggh, uint2* __restrict__ aggl) {
    int w = (blockIdx.x * blockDim.x + threadIdx.x) >> 5;
    if (w >= N) return;
    int lane = threadIdx.x & 31;
    int beg = rs[w], end = rs[w + 1];
    float4 a0 = make_float4(0.f, 0.f, 0.f, 0.f), a1 = a0, a2 = a0, a3 = a0;
    for (int e = beg; e < end; e++) {
        const float4* p = (const float4*)(feat + (size_t)csr[e] * DD);
        float4 v;
        v = p[lane];      a0.x += v.x; a0.y += v.y; a0.z += v.z; a0.w += v.w;
        v = p[lane + 32]; a1.x += v.x; a1.y += v.y; a1.z += v.z; a1.w += v.w;
        v = p[lane + 64]; a2.x += v.x; a2.y += v.y; a2.z += v.z; a2.w += v.w;
        v = p[lane + 96]; a3.x += v.x; a3.y += v.y; a3.z += v.z; a3.w += v.w;
    }
    int deg = end - beg;
    float sc = 1.f / (float)(deg > 1 ? deg : 1);
    a0.x *= sc; a0.y *= sc; a0.z *= sc; a0.w *= sc;
    a1.x *= sc; a1.y *= sc; a1.z *= sc; a1.w *= sc;
    a2.x *= sc; a2.y *= sc; a2.z *= sc; a2.w *= sc;
    a3.x *= sc; a3.y *= sc; a3.z *= sc; a3.w *= sc;
    size_t rb = (size_t)w * (DD / 4);
    uint2 h, l;
    split4(a0, h, l); aggh[rb + lane]      = h; aggl[rb + lane]      = l;
    split4(a1, h, l); aggh[rb + lane + 32] = h; aggl[rb + lane + 32] = l;
    split4(a2, h, l); aggh[rb + lane + 64] = h; aggl[rb + lane + 64] = l;
    split4(a3, h, l); aggh[rb + lane + 96] = h; aggl[rb + lane + 96] = l;
}

// ================= bias precombination =================
__global__ void biascomb_k(const float* __restrict__ bn, const float* __restrict__ bs,
                           const float* __restrict__ bu, const float* __restrict__ Wu,
                           float* __restrict__ bp) {
    int j = blockIdx.x * blockDim.x + threadIdx.x;
    if (j >= DD) return;
    const float* WuT = Wu;
    const float* WuB = Wu + DD * DD;
    float acc = bu[j];
    for (int k = 0; k < DD; k++)
        acc += bn[k] * WuT[k * DD + j] + bs[k] * WuB[k * DD + j];
    bp[j] = acc;
}

// ================= batched fp32 512^3 precombine GEMM =================
struct PrePtrs { const float* A[8]; const float* Bm[8]; float* C[8]; };

__global__ __launch_bounds__(256, 2) void gemm_pre_k(PrePtrs p) {
    const float* A = p.A[blockIdx.z];
    const float* W = p.Bm[blockIdx.z];
    float* C = p.C[blockIdx.z];
    __shared__ float As[16][128];
    __shared__ float Bs[16][128];
    const int tid = threadIdx.x;
    const int tx = tid & 15, ty = tid >> 4;
    const int row0 = blockIdx.y * 128, col0 = blockIdx.x * 128;
    float acc[8][8];
#pragma unroll
    for (int i = 0; i < 8; i++)
#pragma unroll
        for (int j = 0; j < 8; j++) acc[i][j] = 0.f;
    const int lm = tid >> 1, lk = (tid & 1) * 8;
    const int wk = tid >> 4, wc = (tid & 15) * 8;
    for (int kk = 0; kk < 512; kk += 16) {
        const float* pA = A + (size_t)(row0 + lm) * 512 + kk + lk;
        float4 a0 = *(const float4*)pA, a1 = *(const float4*)(pA + 4);
        const float* pW = W + (size_t)(kk + wk) * 512 + col0 + wc;
        float4 w0 = *(const float4*)pW, w1 = *(const float4*)(pW + 4);
        As[lk + 0][lm] = a0.x; As[lk + 1][lm] = a0.y;
        As[lk + 2][lm] = a0.z; As[lk + 3][lm] = a0.w;
        As[lk + 4][lm] = a1.x; As[lk + 5][lm] = a1.y;
        As[lk + 6][lm] = a1.z; As[lk + 7][lm] = a1.w;
        *(float4*)&Bs[wk][wc] = w0;
        *(float4*)&Bs[wk][wc + 4] = w1;
        __syncthreads();
#pragma unroll
        for (int k = 0; k < 16; k++) {
            float ra[8], rb[8];
            *(float4*)&ra[0] = *(const float4*)&As[k][ty * 8];
            *(float4*)&ra[4] = *(const float4*)&As[k][ty * 8 + 4];
            *(float4*)&rb[0] = *(const float4*)&Bs[k][tx * 8];
            *(float4*)&rb[4] = *(const float4*)&Bs[k][tx * 8 + 4];
#pragma unroll
            for (int i = 0; i < 8; i++)
#pragma unroll
                for (int j = 0; j < 8; j++) acc[i][j] += ra[i] * rb[j];
        }
        __syncthreads();
    }
#pragma unroll
    for (int i = 0; i < 8; i++) {
        float* cp = C + (size_t)(row0 + ty * 8 + i) * 512 + col0 + tx * 8;
        *(float4*)cp = make_float4(acc[i][0], acc[i][1], acc[i][2], acc[i][3]);
        *(float4*)(cp + 4) = make_float4(acc[i][4], acc[i][5], acc[i][6], acc[i][7]);
    }
}

// ================= bf16-split tensor-core GEMM =================
// C[M,512] = A0@W0 + A1@W1 + bias  with A = Ah + Al, W = Wh + Wl (bf16 split)
// tile 128x128, 256 threads, cp.async double buffer, mma.sync m16n8k16

#define APAD 40
#define BPAD 136
#define A_T (128 * APAD)
#define B_T (32 * BPAD)
#define STG (2 * A_T + 2 * B_T)
#define GEMM_SMEM (STG * 2 * 2)   // 2 stages * bytes

__device__ __forceinline__ void cp16(uint32_t s, const void* g, int p16) {
    asm volatile("cp.async.cg.shared.global [%0], [%1], 16, %2;\n"
                 :: "r"(s), "l"(g), "r"(p16));
}

#define LDSM4(R, addr) \
    asm volatile("ldmatrix.sync.aligned.m8n8.x4.shared.b16 {%0,%1,%2,%3},[%4];\n" \
        : "=r"((R)[0]), "=r"((R)[1]), "=r"((R)[2]), "=r"((R)[3]) : "r"(addr))

#define LDSM4T(r0, r1, r2, r3, addr) \
    asm volatile("ldmatrix.sync.aligned.m8n8.x4.trans.shared.b16 {%0,%1,%2,%3},[%4];\n" \
        : "=r"(r0), "=r"(r1), "=r"(r2), "=r"(r3) : "r"(addr))

#define MMA16816(D, Af, Bf) \
    asm volatile("mma.sync.aligned.m16n8k16.row.col.f32.bf16.bf16.f32 " \
        "{%0,%1,%2,%3},{%4,%5,%6,%7},{%8,%9},{%0,%1,%2,%3};\n" \
        : "+f"((D)[0]), "+f"((D)[1]), "+f"((D)[2]), "+f"((D)[3]) \
        : "r"((Af)[0]), "r"((Af)[1]), "r"((Af)[2]), "r"((Af)[3]), \
          "r"((Bf)[0]), "r"((Bf)[1]))

__global__ __launch_bounds__(256, 1) void gemm_bf16_k(
    const bf16* __restrict__ A0h, const bf16* __restrict__ A0l,
    const bf16* __restrict__ W0h, const bf16* __restrict__ W0l,
    const bf16* __restrict__ A1h, const bf16* __restrict__ A1l,
    const bf16* __restrict__ W1h, const bf16* __restrict__ W1l,
    const float* __restrict__ bias, float* __restrict__ C, int M) {
    extern __shared__ bf16 smdyn[];
    uint32_t smb = (uint32_t)__cvta_generic_to_shared(smdyn);
    const int tid = threadIdx.x;
    const int lane = tid & 31;
    const int wid = tid >> 5;
    const int warp_m = wid & 1, warp_n = wid >> 1;
    const int row0 = blockIdx.y * 128, col0 = blockIdx.x * 128;

    float acc[16][4];
#pragma unroll
    for (int i = 0; i < 16; i++) { acc[i][0] = acc[i][1] = acc[i][2] = acc[i][3] = 0.f; }

    // loader mapping
    const int arow = tid >> 1, ac0 = (tid & 1) * 16;
    const int brow = tid >> 3, bc0 = (tid & 7) * 16;
    const int agrow = row0 + arow;
    const int apred = (agrow < M) ? 16 : 0;
    const size_t aoff = (size_t)(agrow < M ? agrow : (M - 1)) * DD;

    auto issue = [&](int s) {
        const int ph = s >> 4;
        const int k0 = (s & 15) * 32;
        const int buf = s & 1;
        const bf16* Ah = ph ? A1h : A0h;
        const bf16* Al = ph ? A1l : A0l;
        const bf16* Wh = ph ? W1h : W0h;
        const bf16* Wl = ph ? W1l : W0l;
        uint32_t base = smb + buf * (STG * 2);
        uint32_t sa = base + (arow * APAD + ac0) * 2;
        const bf16* ga = Ah + aoff + k0 + ac0;
        cp16(sa, ga, apred);
        cp16(sa + 16, ga + 8, apred);
        uint32_t sal = base + (A_T + arow * APAD + ac0) * 2;
        const bf16* gal = Al + aoff + k0 + ac0;
        cp16(sal, gal, apred);
        cp16(sal + 16, gal + 8, apred);
        uint32_t sb = base + (2 * A_T + brow * BPAD + bc0) * 2;
        const bf16* gb = Wh + (size_t)(k0 + brow) * DD + col0 + bc0;
        cp16(sb, gb, 16);
        cp16(sb + 16, gb + 8, 16);
        uint32_t sbl = base + (2 * A_T + B_T + brow * BPAD + bc0) * 2;
        const bf16* gbl = Wl + (size_t)(k0 + brow) * DD + col0 + bc0;
        cp16(sbl, gbl, 16);
        cp16(sbl + 16, gbl + 8, 16);
        asm volatile("cp.async.commit_group;\n");
    };

    const int am = warp_m * 64 + (lane & 15);
    const int akoff = (lane >> 4) << 3;           // 0 or 8
    const int bk = lane & 15;
    const int bn = warp_n * 32 + ((lane & 16) ? 8 : 0);

    issue(0);
#pragma unroll 1
    for (int s = 0; s < 32; s++) {
        if (s + 1 < 32) {
            issue(s + 1);
            asm volatile("cp.async.wait_group 1;\n");
        } else {
            asm volatile("cp.async.wait_group 0;\n");
        }
        __syncthreads();
        const int buf = s & 1;
        uint32_t base = smb + buf * (STG * 2);
        uint32_t Ab = base;
        uint32_t Alb = base + A_T * 2;
        uint32_t Bb = base + 2 * A_T * 2;
        uint32_t Blb = Bb + B_T * 2;
#pragma unroll
        for (int kk = 0; kk < 32; kk += 16) {
            uint32_t ah[4][4], al[4][4], bh[4][2], bl[4][2];
#pragma unroll
            for (int mt = 0; mt < 4; mt++) {
                uint32_t off = ((am + mt * 16) * APAD + kk + akoff) * 2;
                LDSM4(ah[mt], Ab + off);
                LDSM4(al[mt], Alb + off);
            }
#pragma unroll
            for (int pr = 0; pr < 2; pr++) {
                uint32_t off = ((kk + bk) * BPAD + bn + pr * 16) * 2;
                uint32_t r0, r1, r2, r3;
                LDSM4T(r0, r1, r2, r3, Bb + off);
                bh[2 * pr][0] = r0; bh[2 * pr][1] = r1;
                bh[2 * pr + 1][0] = r2; bh[2 * pr + 1][1] = r3;
                LDSM4T(r0, r1, r2, r3, Blb + off);
                bl[2 * pr][0] = r0; bl[2 * pr][1] = r1;
                bl[2 * pr + 1][0] = r2; bl[2 * pr + 1][1] = r3;
            }
#pragma unroll
            for (int mt = 0; mt < 4; mt++)
#pragma unroll
                for (int nt = 0; nt < 4; nt++) {
                    MMA16816(acc[mt * 4 + nt], ah[mt], bh[nt]);
                    MMA16816(acc[mt * 4 + nt], ah[mt], bl[nt]);
                    MMA16816(acc[mt * 4 + nt], al[mt], bh[nt]);
                }
        }
        __syncthreads();
    }

    // epilogue
    const int er = row0 + warp_m * 64 + (lane >> 2);
    const int ec = col0 + warp_n * 32 + (lane & 3) * 2;
#pragma unroll
    for (int mt = 0; mt < 4; mt++) {
#pragma unroll
        for (int nt = 0; nt < 4; nt++) {
            int c = ec + nt * 8;
            float b0 = bias[c], b1 = bias[c + 1];
            int r = er + mt * 16;
            if (r < M) {
                float2 v = make_float2(acc[mt * 4 + nt][0] + b0, acc[mt * 4 + nt][1] + b1);
                *(float2*)(C + (size_t)r * DD + c) = v;
            }
            if (r + 8 < M) {
                float2 v = make_float2(acc[mt * 4 + nt][2] + b0, acc[mt * 4 + nt][3] + b1);
                *(float2*)(C + (size_t)(r + 8) * DD + c) = v;
            }
        }
    }
}

// ================= host orchestration =================
static void build_csr(const int* ei, int E, int N, int* cnt, int* part, int* bsum,
                      int* cur, int* rs, int* csr) {
    cudaMemsetAsync(cnt, 0, (size_t)N * sizeof(int));
    hist_k<<<(E + 255) / 256, 256>>>(ei, E, cnt);
    int nb = (N + 1023) / 1024;
    scan1_k<<<nb, 1024>>>(cnt, N, part, bsum);
    scan2_k<<<1, 128>>>(bsum, nb);
    scan3_k<<<nb, 1024>>>(part, bsum, rs, N);
    cudaMemsetAsync(cur, 0, (size_t)N * sizeof(int));
    fill_k<<<(E + 255) / 256, 256>>>(ei, E, rs, cur, csr);
}

static void run_sage(const float* hsrc, const bf16* hdh, const bf16* hdl,
                     const int* csr, const int* rs, int Nd,
                     const bf16* Wnh, const bf16* Wnl, const bf16* Wsh, const bf16* Wsl,
                     const float* bias, float* out, bf16* aggh, bf16* aggl) {
    gather_k<<<(Nd + 7) / 8, 256>>>(hsrc, csr, rs, Nd, (uint2*)aggh, (uint2*)aggl);
    dim3 g(4, (Nd + 127) / 128);
    gemm_bf16_k<<<g, 256, GEMM_SMEM>>>(aggh, aggl, Wnh, Wnl, hdh, hdl, Wsh, Wsl,
                                       bias, out, Nd);
}

extern "C" void kernel_launch(void* const* d_in, const int* in_sizes, int n_in,
                              void* d_out, int out_size) {
    const float* x0 = (const float*)d_in[0];
    const float* x1 = (const float*)d_in[1];
    const int* ei01 = (const int*)d_in[2];
    const int* ei10 = (const int*)d_in[3];
    const int N0 = in_sizes[0] / DD;
    const int N1 = in_sizes[1] / DD;
    const int E01 = in_sizes[2] / 2;
    const int E10 = in_sizes[3] / 2;

    float *h0, *h1, *o0, *o1, *Wp, *bp;
    bf16 *h0h, *h0l, *h1h, *h1l, *aggh, *aggl, *Wph, *Wpl;
    int *csr01, *csr10, *rs01, *rs10, *cnt, *part, *bsum, *cur;
    cudaGetSymbolAddress((void**)&h0, g_h0);
    cudaGetSymbolAddress((void**)&h1, g_h1);
    cudaGetSymbolAddress((void**)&o0, g_o0);
    cudaGetSymbolAddress((void**)&o1, g_o1);
    cudaGetSymbolAddress((void**)&h0h, g_h0h);
    cudaGetSymbolAddress((void**)&h0l, g_h0l);
    cudaGetSymbolAddress((void**)&h1h, g_h1h);
    cudaGetSymbolAddress((void**)&h1l, g_h1l);
    cudaGetSymbolAddress((void**)&aggh, g_aggh);
    cudaGetSymbolAddress((void**)&aggl, g_aggl);
    cudaGetSymbolAddress((void**)&Wp, g_Wp);
    cudaGetSymbolAddress((void**)&Wph, g_Wph);
    cudaGetSymbolAddress((void**)&Wpl, g_Wpl);
    cudaGetSymbolAddress((void**)&bp, g_bp);
    cudaGetSymbolAddress((void**)&csr01, g_csr01);
    cudaGetSymbolAddress((void**)&csr10, g_csr10);
    cudaGetSymbolAddress((void**)&rs01, g_rs01);
    cudaGetSymbolAddress((void**)&rs10, g_rs10);
    cudaGetSymbolAddress((void**)&cnt, g_cnt);
    cudaGetSymbolAddress((void**)&part, g_part);
    cudaGetSymbolAddress((void**)&bsum, g_bsum);
    cudaGetSymbolAddress((void**)&cur, g_cur);

    cudaFuncSetAttribute(gemm_bf16_k, cudaFuncAttributeMaxDynamicSharedMemorySize,
                         GEMM_SMEM);

    // ---- CSR build (edge structure is layer-invariant) ----
    build_csr(ei01, E01, N1, cnt, part, bsum, cur, rs01, csr01);
    build_csr(ei10, E10, N0, cnt, part, bsum, cur, rs10, csr10);

    // ---- precombine weights: Wp[2s]=Wn@WuT, Wp[2s+1]=Ws@WuB ----
    PrePtrs pp;
    for (int s = 0; s < 4; s++) {
        const float* Wn = (const float*)d_in[4 + 6 * s + 0];
        const float* bn = (const float*)d_in[4 + 6 * s + 1];
        const float* Ws_ = (const float*)d_in[4 + 6 * s + 2];
        const float* bs = (const float*)d_in[4 + 6 * s + 3];
        const float* Wu = (const float*)d_in[4 + 6 * s + 4];
        const float* bu = (const float*)d_in[4 + 6 * s + 5];
        pp.A[2 * s] = Wn;      pp.Bm[2 * s] = Wu;
        pp.C[2 * s] = Wp + (size_t)(2 * s) * DD * DD;
        pp.A[2 * s + 1] = Ws_; pp.Bm[2 * s + 1] = Wu + DD * DD;
        pp.C[2 * s + 1] = Wp + (size_t)(2 * s + 1) * DD * DD;
        biascomb_k<<<2, 256>>>(bn, bs, bu, Wu, bp + s * DD);
    }
    {
        dim3 g(4, 4, 8);
        gemm_pre_k<<<g, 256>>>(pp);
    }
    {
        int n4 = 8 * DD * DD / 4;
        wconv_k<<<(n4 + 255) / 256, 256>>>((const float4*)Wp, (uint2*)Wph, (uint2*)Wpl, n4);
    }

    const int n40 = N0 * (DD / 4);
    const int n41 = N1 * (DD / 4);

    // ---- layer 1 ----
    hfuse_k<<<(n40 + 255) / 256, 256>>>((const float4*)x0, (float4*)h0,
                                        (uint2*)h0h, (uint2*)h0l, n40);
    hfuse_k<<<(n41 + 255) / 256, 256>>>((const float4*)x1, (float4*)h1,
                                        (uint2*)h1h, (uint2*)h1l, n41);
    run_sage(h0, h1h, h1l, csr01, rs01, N1,
             Wph + (size_t)0 * DD * DD, Wpl + (size_t)0 * DD * DD,
             Wph + (size_t)1 * DD * DD, Wpl + (size_t)1 * DD * DD,
             bp + 0 * DD, o1, aggh, aggl);
    run_sage(h1, h0h, h0l, csr10, rs10, N0,
             Wph + (size_t)2 * DD * DD, Wpl + (size_t)2 * DD * DD,
             Wph + (size_t)3 * DD * DD, Wpl + (size_t)3 * DD * DD,
             bp + 1 * DD, o0, aggh, aggl);

    // ---- layer 2 ----
    hfuse_k<<<(n40 + 255) / 256, 256>>>((const float4*)o0, (float4*)h0,
                                        (uint2*)h0h, (uint2*)h0l, n40);
    hfuse_k<<<(n41 + 255) / 256, 256>>>((const float4*)o1, (float4*)h1,
                                        (uint2*)h1h, (uint2*)h1l, n41);

    float* out0 = (float*)d_out;
    float* out1 = out0 + (size_t)N0 * DD;
    run_sage(h0, h1h, h1l, csr01, rs01, N1,
             Wph + (size_t)4 * DD * DD, Wpl + (size_t)4 * DD * DD,
             Wph + (size_t)5 * DD * DD, Wpl + (size_t)5 * DD * DD,
             bp + 2 * DD, out1, aggh, aggl);
    run_sage(h1, h0h, h0l, csr10, rs10, N0,
             Wph + (size_t)6 * DD * DD, Wpl + (size_t)6 * DD * DD,
             Wph + (size_t)7 * DD * DD, Wpl + (size_t)7 * DD * DD,
             bp + 3 * DD, out0, aggh, aggl);
}

// round 7
// speedup vs baseline: 2.9849x; 1.0918x over previous
#include <cuda_runtime.h>
#include <cuda_bf16.h>
#include <cstdint>
#include <cstddef>

#define DD 512
#define NNODE 100000
#define EMAX 1000000
typedef __nv_bfloat16 bf16;

// ---- static device scratch (allocation-free rule) ----
__device__ float g_o0[NNODE * DD];
__device__ float g_o1[NNODE * DD];
__device__ bf16  g_h0h[NNODE * DD];
__device__ bf16  g_h0l[NNODE * DD];
__device__ bf16  g_h1h[NNODE * DD];
__device__ bf16  g_h1l[NNODE * DD];
__device__ bf16  g_s0h[NNODE * DD];
__device__ bf16  g_s0l[NNODE * DD];
__device__ bf16  g_s1h[NNODE * DD];
__device__ bf16  g_s1l[NNODE * DD];
__device__ bf16  g_aggh[NNODE * DD];
__device__ bf16  g_aggl[NNODE * DD];
__device__ float g_Wp[8 * DD * DD];
__device__ bf16  g_Wph[8 * DD * DD];
__device__ bf16  g_Wpl[8 * DD * DD];
__device__ float g_bp[4 * DD];
__device__ int   g_csr01[EMAX];
__device__ int   g_csr10[EMAX];
__device__ int   g_rs01[NNODE + 1];
__device__ int   g_rs10[NNODE + 1];
__device__ int   g_cnt[NNODE];
__device__ int   g_part[NNODE];
__device__ int   g_bsum[256];
__device__ int   g_cur[NNODE];

// ================= helpers =================
__device__ __forceinline__ void split4(float4 v, uint2& h, uint2& l) {
    bf16 hx = __float2bfloat16(v.x), hy = __float2bfloat16(v.y);
    bf16 hz = __float2bfloat16(v.z), hw = __float2bfloat16(v.w);
    bf16 lx = __float2bfloat16(v.x - __bfloat162float(hx));
    bf16 ly = __float2bfloat16(v.y - __bfloat162float(hy));
    bf16 lz = __float2bfloat16(v.z - __bfloat162float(hz));
    bf16 lw = __float2bfloat16(v.w - __bfloat162float(hw));
    h.x = ((uint32_t)__bfloat16_as_ushort(hy) << 16) | __bfloat16_as_ushort(hx);
    h.y = ((uint32_t)__bfloat16_as_ushort(hw) << 16) | __bfloat16_as_ushort(hz);
    l.x = ((uint32_t)__bfloat16_as_ushort(ly) << 16) | __bfloat16_as_ushort(lx);
    l.y = ((uint32_t)__bfloat16_as_ushort(lw) << 16) | __bfloat16_as_ushort(lz);
}
__device__ __forceinline__ float4 lrelu4(float4 v) {
    v.x = v.x > 0.f ? v.x : 0.01f * v.x;
    v.y = v.y > 0.f ? v.y : 0.01f * v.y;
    v.z = v.z > 0.f ? v.z : 0.01f * v.z;
    v.w = v.w > 0.f ? v.w : 0.01f * v.w;
    return v;
}
__device__ __forceinline__ uint32_t pack2h(float a, float b) {
    return ((uint32_t)__bfloat16_as_ushort(__float2bfloat16(b)) << 16) |
           __bfloat16_as_ushort(__float2bfloat16(a));
}

// ================= elementwise: lrelu -> bf16 hi/lo split =================
__global__ void hsplit_k(const float4* __restrict__ in, uint2* __restrict__ hi,
                         uint2* __restrict__ lo, int n4) {
    int i = blockIdx.x * blockDim.x + threadIdx.x;
    if (i >= n4) return;
    float4 v = lrelu4(in[i]);
    uint2 h, l;
    split4(v, h, l);
    hi[i] = h; lo[i] = l;
}

// weight fp32 -> bf16 hi/lo
__global__ void wconv_k(const float4* __restrict__ in, uint2* __restrict__ hi,
                        uint2* __restrict__ lo, int n4) {
    int i = blockIdx.x * blockDim.x + threadIdx.x;
    if (i >= n4) return;
    uint2 h, l;
    split4(in[i], h, l);
    hi[i] = h; lo[i] = l;
}

// ================= CSR build =================
__global__ void hist_k(const int* __restrict__ ei, int E, int* __restrict__ cnt) {
    int e = blockIdx.x * blockDim.x + threadIdx.x;
    if (e < E) atomicAdd(&cnt[ei[E + e]], 1);
}
__global__ void scan1_k(const int* __restrict__ cnt, int N, int* __restrict__ part,
                        int* __restrict__ bsum) {
    __shared__ int sh[1024];
    int t = threadIdx.x;
    int i = blockIdx.x * 1024 + t;
    sh[t] = (i < N) ? cnt[i] : 0;
    __syncthreads();
    for (int off = 1; off < 1024; off <<= 1) {
        int v = (t >= off) ? sh[t - off] : 0;
        __syncthreads();
        sh[t] += v;
        __syncthreads();
    }
    if (i < N) part[i] = sh[t];
    if (t == 1023) bsum[blockIdx.x] = sh[1023];
}
__global__ void scan2_k(int* __restrict__ bsum, int nb) {
    __shared__ int sh[128];
    int t = threadIdx.x;
    sh[t] = (t < nb) ? bsum[t] : 0;
    __syncthreads();
    for (int off = 1; off < 128; off <<= 1) {
        int v = (t >= off) ? sh[t - off] : 0;
        __syncthreads();
        sh[t] += v;
        __syncthreads();
    }
    if (t < nb) bsum[t] = sh[t];
}
__global__ void scan3_k(const int* __restrict__ part, const int* __restrict__ bsum,
                        int* __restrict__ rs, int N) {
    int i = blockIdx.x * blockDim.x + threadIdx.x;
    if (i < N) {
        int b = i >> 10;
        int off = (b > 0) ? bsum[b - 1] : 0;
        rs[i + 1] = part[i] + off;
    }
    if (i == 0) rs[0] = 0;
}
__global__ void fill_k(const int* __restrict__ ei, int E, const int* __restrict__ rs,
                       int* __restrict__ cur, int* __restrict__ csr) {
    int e = blockIdx.x * blockDim.x + threadIdx.x;
    if (e >= E) return;
    int s = ei[e], d = ei[E + e];
    int pos = atomicAdd(&cur[d], 1);
    csr[rs[d] + pos] = s;
}

// ================= CSR gather: mean of lrelu(feat) -> bf16 hi/lo =================
__global__ void gather_k(const float* __restrict__ feat, const int* __restrict__ csr,
                         const int* __restrict__ rs, int N,
                         uint2* __restrict__ aggh, uint2* __restrict__ aggl) {
    int w = (blockIdx.x * blockDim.x + threadIdx.x) >> 5;
    if (w >= N) return;
    int lane = threadIdx.x & 31;
    int beg = rs[w], end = rs[w + 1];
    float4 a0 = make_float4(0.f, 0.f, 0.f, 0.f), a1 = a0, a2 = a0, a3 = a0;
    for (int e = beg; e < end; e++) {
        const float4* p = (const float4*)(feat + (size_t)csr[e] * DD);
        float4 v;
        v = lrelu4(p[lane]);      a0.x += v.x; a0.y += v.y; a0.z += v.z; a0.w += v.w;
        v = lrelu4(p[lane + 32]); a1.x += v.x; a1.y += v.y; a1.z += v.z; a1.w += v.w;
        v = lrelu4(p[lane + 64]); a2.x += v.x; a2.y += v.y; a2.z += v.z; a2.w += v.w;
        v = lrelu4(p[lane + 96]); a3.x += v.x; a3.y += v.y; a3.z += v.z; a3.w += v.w;
    }
    int deg = end - beg;
    float sc = 1.f / (float)(deg > 1 ? deg : 1);
    a0.x *= sc; a0.y *= sc; a0.z *= sc; a0.w *= sc;
    a1.x *= sc; a1.y *= sc; a1.z *= sc; a1.w *= sc;
    a2.x *= sc; a2.y *= sc; a2.z *= sc; a2.w *= sc;
    a3.x *= sc; a3.y *= sc; a3.z *= sc; a3.w *= sc;
    size_t rb = (size_t)w * (DD / 4);
    uint2 h, l;
    split4(a0, h, l); aggh[rb + lane]      = h; aggl[rb + lane]      = l;
    split4(a1, h, l); aggh[rb + lane + 32] = h; aggl[rb + lane + 32] = l;
    split4(a2, h, l); aggh[rb + lane + 64] = h; aggl[rb + lane + 64] = l;
    split4(a3, h, l); aggh[rb + lane + 96] = h; aggl[rb + lane + 96] = l;
}

// ================= bias precombination =================
__global__ void biascomb_k(const float* __restrict__ bn, const float* __restrict__ bs,
                           const float* __restrict__ bu, const float* __restrict__ Wu,
                           float* __restrict__ bp) {
    int j = blockIdx.x * blockDim.x + threadIdx.x;
    if (j >= DD) return;
    const float* WuT = Wu;
    const float* WuB = Wu + DD * DD;
    float acc = bu[j];
    for (int k = 0; k < DD; k++)
        acc += bn[k] * WuT[k * DD + j] + bs[k] * WuB[k * DD + j];
    bp[j] = acc;
}

// ================= batched fp32 512^3 precombine GEMM =================
struct PrePtrs { const float* A[8]; const float* Bm[8]; float* C[8]; };

__global__ __launch_bounds__(256, 2) void gemm_pre_k(PrePtrs p) {
    const float* A = p.A[blockIdx.z];
    const float* W = p.Bm[blockIdx.z];
    float* C = p.C[blockIdx.z];
    __shared__ float As[16][128];
    __shared__ float Bs[16][128];
    const int tid = threadIdx.x;
    const int tx = tid & 15, ty = tid >> 4;
    const int row0 = blockIdx.y * 128, col0 = blockIdx.x * 128;
    float acc[8][8];
#pragma unroll
    for (int i = 0; i < 8; i++)
#pragma unroll
        for (int j = 0; j < 8; j++) acc[i][j] = 0.f;
    const int lm = tid >> 1, lk = (tid & 1) * 8;
    const int wk = tid >> 4, wc = (tid & 15) * 8;
    for (int kk = 0; kk < 512; kk += 16) {
        const float* pA = A + (size_t)(row0 + lm) * 512 + kk + lk;
        float4 a0 = *(const float4*)pA, a1 = *(const float4*)(pA + 4);
        const float* pW = W + (size_t)(kk + wk) * 512 + col0 + wc;
        float4 w0 = *(const float4*)pW, w1 = *(const float4*)(pW + 4);
        As[lk + 0][lm] = a0.x; As[lk + 1][lm] = a0.y;
        As[lk + 2][lm] = a0.z; As[lk + 3][lm] = a0.w;
        As[lk + 4][lm] = a1.x; As[lk + 5][lm] = a1.y;
        As[lk + 6][lm] = a1.z; As[lk + 7][lm] = a1.w;
        *(float4*)&Bs[wk][wc] = w0;
        *(float4*)&Bs[wk][wc + 4] = w1;
        __syncthreads();
#pragma unroll
        for (int k = 0; k < 16; k++) {
            float ra[8], rb[8];
            *(float4*)&ra[0] = *(const float4*)&As[k][ty * 8];
            *(float4*)&ra[4] = *(const float4*)&As[k][ty * 8 + 4];
            *(float4*)&rb[0] = *(const float4*)&Bs[k][tx * 8];
            *(float4*)&rb[4] = *(const float4*)&Bs[k][tx * 8 + 4];
#pragma unroll
            for (int i = 0; i < 8; i++)
#pragma unroll
                for (int j = 0; j < 8; j++) acc[i][j] += ra[i] * rb[j];
        }
        __syncthreads();
    }
#pragma unroll
    for (int i = 0; i < 8; i++) {
        float* cp = C + (size_t)(row0 + ty * 8 + i) * 512 + col0 + tx * 8;
        *(float4*)cp = make_float4(acc[i][0], acc[i][1], acc[i][2], acc[i][3]);
        *(float4*)(cp + 4) = make_float4(acc[i][4], acc[i][5], acc[i][6], acc[i][7]);
    }
}

// ================= bf16-split tensor-core GEMM (mma.sync) =================
// C[M,512] = A0@W0 + A1@W1 + bias, A = Ah+Al, W = Wh+Wl (bf16 split, 3 passes)
// 128x128 tile, K chunk 32, 3-stage cp.async ring, 2 CTAs/SM.
// NST = 2 phases * 16 K-chunks = 32 stages.   <-- R6 bug was NST=16 (half of K)
// Optional fused epilogue: split(lrelu(C)) -> hi/lo bf16.

#define APAD 40
#define BPAD 136
#define A_T (128 * APAD)
#define B_T (32 * BPAD)
#define STG (2 * A_T + 2 * B_T)          // elems per stage
#define NSTAGE 3
#define GEMM_SMEM (NSTAGE * STG * 2)     // bytes (113,664)
#define NST 32                            // 2 phases * (512/32)

__device__ __forceinline__ void cp16(uint32_t s, const void* g, int p16) {
    asm volatile("cp.async.cg.shared.global [%0], [%1], 16, %2;\n"
                 :: "r"(s), "l"(g), "r"(p16));
}

#define LDSM4(R, addr) \
    asm volatile("ldmatrix.sync.aligned.m8n8.x4.shared.b16 {%0,%1,%2,%3},[%4];\n" \
        : "=r"((R)[0]), "=r"((R)[1]), "=r"((R)[2]), "=r"((R)[3]) : "r"(addr))

#define LDSM4T(r0, r1, r2, r3, addr) \
    asm volatile("ldmatrix.sync.aligned.m8n8.x4.trans.shared.b16 {%0,%1,%2,%3},[%4];\n" \
        : "=r"(r0), "=r"(r1), "=r"(r2), "=r"(r3) : "r"(addr))

#define MMA16816(D, Af, Bf) \
    asm volatile("mma.sync.aligned.m16n8k16.row.col.f32.bf16.bf16.f32 " \
        "{%0,%1,%2,%3},{%4,%5,%6,%7},{%8,%9},{%0,%1,%2,%3};\n" \
        : "+f"((D)[0]), "+f"((D)[1]), "+f"((D)[2]), "+f"((D)[3]) \
        : "r"((Af)[0]), "r"((Af)[1]), "r"((Af)[2]), "r"((Af)[3]), \
          "r"((Bf)[0]), "r"((Bf)[1]))

__global__ __launch_bounds__(256, 2) void gemm_bf16_k(
    const bf16* __restrict__ A0h, const bf16* __restrict__ A0l,
    const bf16* __restrict__ W0h, const bf16* __restrict__ W0l,
    const bf16* __restrict__ A1h, const bf16* __restrict__ A1l,
    const bf16* __restrict__ W1h, const bf16* __restrict__ W1l,
    const float* __restrict__ bias, float* __restrict__ C,
    uint32_t* __restrict__ SplitH, uint32_t* __restrict__ SplitL, int M) {
    extern __shared__ bf16 smdyn[];
    uint32_t smb = (uint32_t)__cvta_generic_to_shared(smdyn);
    const int tid = threadIdx.x;
    const int lane = tid & 31;
    const int wid = tid >> 5;
    const int warp_m = wid & 1, warp_n = wid >> 1;
    const int row0 = blockIdx.y * 128, col0 = blockIdx.x * 128;

    float acc[16][4];
#pragma unroll
    for (int i = 0; i < 16; i++) { acc[i][0] = acc[i][1] = acc[i][2] = acc[i][3] = 0.f; }

    // loader mapping
    const int arow = tid >> 1, ac0 = (tid & 1) * 16;
    const int brow = tid >> 3, bc0 = (tid & 7) * 16;
    const int agrow = row0 + arow;
    const int apred = (agrow < M) ? 16 : 0;
    const size_t aoff = (size_t)(agrow < M ? agrow : 0) * DD;

    auto issue = [&](int s) {
        const int ph = s >> 4;              // phase: 0 = (A0,W0), 1 = (A1,W1)
        const int k0 = (s & 15) * 32;       // K chunk within phase
        const int buf = s % NSTAGE;
        const bf16* Ah = ph ? A1h : A0h;
        const bf16* Al = ph ? A1l : A0l;
        const bf16* Wh = ph ? W1h : W0h;
        const bf16* Wl = ph ? W1l : W0l;
        uint32_t base = smb + buf * (STG * 2);
        uint32_t sa = base + (arow * APAD + ac0) * 2;
        const bf16* ga = Ah + aoff + k0 + ac0;
        cp16(sa, ga, apred);
        cp16(sa + 16, ga + 8, apred);
        uint32_t sal = base + (A_T + arow * APAD + ac0) * 2;
        const bf16* gal = Al + aoff + k0 + ac0;
        cp16(sal, gal, apred);
        cp16(sal + 16, gal + 8, apred);
        uint32_t sb = base + (2 * A_T + brow * BPAD + bc0) * 2;
        const bf16* gb = Wh + (size_t)(k0 + brow) * DD + col0 + bc0;
        cp16(sb, gb, 16);
        cp16(sb + 16, gb + 8, 16);
        uint32_t sbl = base + (2 * A_T + B_T + brow * BPAD + bc0) * 2;
        const bf16* gbl = Wl + (size_t)(k0 + brow) * DD + col0 + bc0;
        cp16(sbl, gbl, 16);
        cp16(sbl + 16, gbl + 8, 16);
        asm volatile("cp.async.commit_group;\n");
    };

    const int am = warp_m * 64 + (lane & 15);
    const int akoff = (lane >> 4) << 3;           // 0 or 8
    const int bk = lane & 15;
    const int bn = warp_n * 32 + ((lane & 16) ? 8 : 0);

    issue(0); issue(1); issue(2);

#pragma unroll 1
    for (int s = 0; s < NST; s++) {
        if (s < NST - 2)       asm volatile("cp.async.wait_group 2;\n" ::: "memory");
        else if (s == NST - 2) asm volatile("cp.async.wait_group 1;\n" ::: "memory");
        else                   asm volatile("cp.async.wait_group 0;\n" ::: "memory");
        __syncthreads();

        const int buf = s % NSTAGE;
        uint32_t base = smb + buf * (STG * 2);
        uint32_t Ab = base;
        uint32_t Alb = base + A_T * 2;
        uint32_t Bb = base + 2 * A_T * 2;
        uint32_t Blb = Bb + B_T * 2;
#pragma unroll
        for (int kk = 0; kk < 32; kk += 16) {
            uint32_t bh[4][2], bl[4][2];
#pragma unroll
            for (int pr = 0; pr < 2; pr++) {
                uint32_t off = ((kk + bk) * BPAD + bn + pr * 16) * 2;
                uint32_t r0, r1, r2, r3;
                LDSM4T(r0, r1, r2, r3, Bb + off);
                bh[2 * pr][0] = r0; bh[2 * pr][1] = r1;
                bh[2 * pr + 1][0] = r2; bh[2 * pr + 1][1] = r3;
                LDSM4T(r0, r1, r2, r3, Blb + off);
                bl[2 * pr][0] = r0; bl[2 * pr][1] = r1;
                bl[2 * pr + 1][0] = r2; bl[2 * pr + 1][1] = r3;
            }
#pragma unroll
            for (int mt = 0; mt < 4; mt++) {
                uint32_t ah[4], al[4];
                uint32_t off = ((am + mt * 16) * APAD + kk + akoff) * 2;
                LDSM4(ah, Ab + off);
                LDSM4(al, Alb + off);
#pragma unroll
                for (int nt = 0; nt < 4; nt++) {
                    MMA16816(acc[mt * 4 + nt], ah, bh[nt]);
                    MMA16816(acc[mt * 4 + nt], ah, bl[nt]);
                    MMA16816(acc[mt * 4 + nt], al, bh[nt]);
                }
            }
        }
        __syncthreads();
        if (s + NSTAGE < NST) issue(s + NSTAGE);
    }

    // epilogue
    const int er = row0 + warp_m * 64 + (lane >> 2);
    const int ec = col0 + warp_n * 32 + (lane & 3) * 2;
#pragma unroll
    for (int mt = 0; mt < 4; mt++) {
#pragma unroll
        for (int nt = 0; nt < 4; nt++) {
            int c = ec + nt * 8;
            float b0 = bias[c], b1 = bias[c + 1];
#pragma unroll
            for (int hh = 0; hh < 2; hh++) {
                int r = er + mt * 16 + hh * 8;
                if (r < M) {
                    float v0 = acc[mt * 4 + nt][2 * hh] + b0;
                    float v1 = acc[mt * 4 + nt][2 * hh + 1] + b1;
                    *(float2*)(C + (size_t)r * DD + c) = make_float2(v0, v1);
                    if (SplitH != nullptr) {
                        float w0 = v0 > 0.f ? v0 : 0.01f * v0;
                        float w1 = v1 > 0.f ? v1 : 0.01f * v1;
                        uint32_t hp = pack2h(w0, w1);
                        bf16 h0b = __ushort_as_bfloat16((unsigned short)(hp & 0xFFFF));
                        bf16 h1b = __ushort_as_bfloat16((unsigned short)(hp >> 16));
                        uint32_t lp = pack2h(w0 - __bfloat162float(h0b),
                                             w1 - __bfloat162float(h1b));
                        size_t o = ((size_t)r * DD + c) >> 1;
                        SplitH[o] = hp;
                        SplitL[o] = lp;
                    }
                }
            }
        }
    }
}

// ================= host orchestration =================
static void build_csr(const int* ei, int E, int N, int* cnt, int* part, int* bsum,
                      int* cur, int* rs, int* csr) {
    cudaMemsetAsync(cnt, 0, (size_t)N * sizeof(int));
    hist_k<<<(E + 255) / 256, 256>>>(ei, E, cnt);
    int nb = (N + 1023) / 1024;
    scan1_k<<<nb, 1024>>>(cnt, N, part, bsum);
    scan2_k<<<1, 128>>>(bsum, nb);
    scan3_k<<<nb, 1024>>>(part, bsum, rs, N);
    cudaMemsetAsync(cur, 0, (size_t)N * sizeof(int));
    fill_k<<<(E + 255) / 256, 256>>>(ei, E, rs, cur, csr);
}

static void run_sage(const float* srcfeat, const bf16* hdh, const bf16* hdl,
                     const int* csr, const int* rs, int Nd,
                     const bf16* Wnh, const bf16* Wnl, const bf16* Wsh, const bf16* Wsl,
                     const float* bias, float* out, bf16* splith, bf16* splitl,
                     bf16* aggh, bf16* aggl) {
    gather_k<<<(Nd + 7) / 8, 256>>>(srcfeat, csr, rs, Nd, (uint2*)aggh, (uint2*)aggl);
    dim3 g(4, (Nd + 127) / 128);
    gemm_bf16_k<<<g, 256, GEMM_SMEM>>>(aggh, aggl, Wnh, Wnl, hdh, hdl, Wsh, Wsl,
                                       bias, out, (uint32_t*)splith, (uint32_t*)splitl, Nd);
}

extern "C" void kernel_launch(void* const* d_in, const int* in_sizes, int n_in,
                              void* d_out, int out_size) {
    const float* x0 = (const float*)d_in[0];
    const float* x1 = (const float*)d_in[1];
    const int* ei01 = (const int*)d_in[2];
    const int* ei10 = (const int*)d_in[3];
    const int N0 = in_sizes[0] / DD;
    const int N1 = in_sizes[1] / DD;
    const int E01 = in_sizes[2] / 2;
    const int E10 = in_sizes[3] / 2;

    float *o0, *o1, *Wp, *bp;
    bf16 *h0h, *h0l, *h1h, *h1l, *s0h, *s0l, *s1h, *s1l, *aggh, *aggl, *Wph, *Wpl;
    int *csr01, *csr10, *rs01, *rs10, *cnt, *part, *bsum, *cur;
    cudaGetSymbolAddress((void**)&o0, g_o0);
    cudaGetSymbolAddress((void**)&o1, g_o1);
    cudaGetSymbolAddress((void**)&h0h, g_h0h);
    cudaGetSymbolAddress((void**)&h0l, g_h0l);
    cudaGetSymbolAddress((void**)&h1h, g_h1h);
    cudaGetSymbolAddress((void**)&h1l, g_h1l);
    cudaGetSymbolAddress((void**)&s0h, g_s0h);
    cudaGetSymbolAddress((void**)&s0l, g_s0l);
    cudaGetSymbolAddress((void**)&s1h, g_s1h);
    cudaGetSymbolAddress((void**)&s1l, g_s1l);
    cudaGetSymbolAddress((void**)&aggh, g_aggh);
    cudaGetSymbolAddress((void**)&aggl, g_aggl);
    cudaGetSymbolAddress((void**)&Wp, g_Wp);
    cudaGetSymbolAddress((void**)&Wph, g_Wph);
    cudaGetSymbolAddress((void**)&Wpl, g_Wpl);
    cudaGetSymbolAddress((void**)&bp, g_bp);
    cudaGetSymbolAddress((void**)&csr01, g_csr01);
    cudaGetSymbolAddress((void**)&csr10, g_csr10);
    cudaGetSymbolAddress((void**)&rs01, g_rs01);
    cudaGetSymbolAddress((void**)&rs10, g_rs10);
    cudaGetSymbolAddress((void**)&cnt, g_cnt);
    cudaGetSymbolAddress((void**)&part, g_part);
    cudaGetSymbolAddress((void**)&bsum, g_bsum);
    cudaGetSymbolAddress((void**)&cur, g_cur);

    cudaFuncSetAttribute(gemm_bf16_k, cudaFuncAttributeMaxDynamicSharedMemorySize,
                         GEMM_SMEM);

    // ---- CSR build ----
    build_csr(ei01, E01, N1, cnt, part, bsum, cur, rs01, csr01);
    build_csr(ei10, E10, N0, cnt, part, bsum, cur, rs10, csr10);

    // ---- precombine weights: Wp[2s]=Wn@WuT, Wp[2s+1]=Ws@WuB ----
    PrePtrs pp;
    for (int s = 0; s < 4; s++) {
        const float* Wn = (const float*)d_in[4 + 6 * s + 0];
        const float* bn = (const float*)d_in[4 + 6 * s + 1];
        const float* Ws_ = (const float*)d_in[4 + 6 * s + 2];
        const float* bs = (const float*)d_in[4 + 6 * s + 3];
        const float* Wu = (const float*)d_in[4 + 6 * s + 4];
        const float* bu = (const float*)d_in[4 + 6 * s + 5];
        pp.A[2 * s] = Wn;      pp.Bm[2 * s] = Wu;
        pp.C[2 * s] = Wp + (size_t)(2 * s) * DD * DD;
        pp.A[2 * s + 1] = Ws_; pp.Bm[2 * s + 1] = Wu + DD * DD;
        pp.C[2 * s + 1] = Wp + (size_t)(2 * s + 1) * DD * DD;
        biascomb_k<<<2, 256>>>(bn, bs, bu, Wu, bp + s * DD);
    }
    {
        dim3 g(4, 4, 8);
        gemm_pre_k<<<g, 256>>>(pp);
    }
    {
        int n4 = 8 * DD * DD / 4;
        wconv_k<<<(n4 + 255) / 256, 256>>>((const float4*)Wp, (uint2*)Wph, (uint2*)Wpl, n4);
    }

    const int n40 = N0 * (DD / 4);
    const int n41 = N1 * (DD / 4);

    // ---- layer 1 self-path splits of lrelu(x) ----
    hsplit_k<<<(n40 + 255) / 256, 256>>>((const float4*)x0, (uint2*)h0h, (uint2*)h0l, n40);
    hsplit_k<<<(n41 + 255) / 256, 256>>>((const float4*)x1, (uint2*)h1h, (uint2*)h1l, n41);

    // l1_01: dst type 1 -> o1 + splits of lrelu(o1) for layer-2 self path
    run_sage(x0, h1h, h1l, csr01, rs01, N1,
             Wph + (size_t)0 * DD * DD, Wpl + (size_t)0 * DD * DD,
             Wph + (size_t)1 * DD * DD, Wpl + (size_t)1 * DD * DD,
             bp + 0 * DD, o1, s1h, s1l, aggh, aggl);
    // l1_10: dst type 0 -> o0 + splits
    run_sage(x1, h0h, h0l, csr10, rs10, N0,
             Wph + (size_t)2 * DD * DD, Wpl + (size_t)2 * DD * DD,
             Wph + (size_t)3 * DD * DD, Wpl + (size_t)3 * DD * DD,
             bp + 1 * DD, o0, s0h, s0l, aggh, aggl);

    // ---- layer 2 ----
    float* out0 = (float*)d_out;
    float* out1 = out0 + (size_t)N0 * DD;
    run_sage(o0, s1h, s1l, csr01, rs01, N1,
             Wph + (size_t)4 * DD * DD, Wpl + (size_t)4 * DD * DD,
             Wph + (size_t)5 * DD * DD, Wpl + (size_t)5 * DD * DD,
             bp + 2 * DD, out1, nullptr, nullptr, aggh, aggl);
    run_sage(o1, s0h, s0l, csr10, rs10, N0,
             Wph + (size_t)6 * DD * DD, Wpl + (size_t)6 * DD * DD,
             Wph + (size_t)7 * DD * DD, Wpl + (size_t)7 * DD * DD,
             bp + 3 * DD, out0, nullptr, nullptr, aggh, aggl);
}

// round 8
// speedup vs baseline: 4.1137x; 1.3782x over previous
#include <cuda_runtime.h>
#include <cuda_fp16.h>
#include <cstdint>
#include <cstddef>

#define DD 512
#define NNODE 100000
#define EMAX 1000000
typedef __half fp16;

// ---- static device scratch (allocation-free rule) ----
__device__ float g_o0[NNODE * DD];
__device__ float g_o1[NNODE * DD];
__device__ fp16  g_h0[NNODE * DD];      // fp16(lrelu(x0)) self path L1
__device__ fp16  g_h1[NNODE * DD];
__device__ fp16  g_s0[NNODE * DD];      // fp16(lrelu(o0)) self path L2
__device__ fp16  g_s1[NNODE * DD];
__device__ fp16  g_agga[NNODE * DD];    // agg for dst type 1
__device__ fp16  g_aggb[NNODE * DD];    // agg for dst type 0
__device__ float g_Wp[8 * DD * DD];
__device__ fp16  g_Wph[8 * DD * DD];
__device__ fp16  g_Wpl[8 * DD * DD];
__device__ float g_bp[4 * DD];
__device__ int   g_csr01[EMAX];
__device__ int   g_csr10[EMAX];
__device__ int   g_rs01[NNODE + 1];
__device__ int   g_rs10[NNODE + 1];
__device__ int   g_cnt[NNODE];
__device__ int   g_part[NNODE];
__device__ int   g_bsum[256];
__device__ int   g_cur[NNODE];

// ================= helpers =================
__device__ __forceinline__ float4 lrelu4(float4 v) {
    v.x = v.x > 0.f ? v.x : 0.01f * v.x;
    v.y = v.y > 0.f ? v.y : 0.01f * v.y;
    v.z = v.z > 0.f ? v.z : 0.01f * v.z;
    v.w = v.w > 0.f ? v.w : 0.01f * v.w;
    return v;
}
__device__ __forceinline__ uint2 pack4h(float4 v) {
    __half2 a = __floats2half2_rn(v.x, v.y);
    __half2 b = __floats2half2_rn(v.z, v.w);
    uint2 r;
    r.x = *(uint32_t*)&a;
    r.y = *(uint32_t*)&b;
    return r;
}

// ================= elementwise: lrelu -> fp16 =================
__global__ void hhalf_k(const float4* __restrict__ in, uint2* __restrict__ out, int n4) {
    int i = blockIdx.x * blockDim.x + threadIdx.x;
    if (i >= n4) return;
    out[i] = pack4h(lrelu4(in[i]));
}

// weight fp32 -> fp16 hi/lo pair
__global__ void wconv_k(const float4* __restrict__ in, uint2* __restrict__ hi,
                        uint2* __restrict__ lo, int n4) {
    int i = blockIdx.x * blockDim.x + threadIdx.x;
    if (i >= n4) return;
    float4 v = in[i];
    fp16 hx = __float2half_rn(v.x), hy = __float2half_rn(v.y);
    fp16 hz = __float2half_rn(v.z), hw = __float2half_rn(v.w);
    float4 l = make_float4(v.x - __half2float(hx), v.y - __half2float(hy),
                           v.z - __half2float(hz), v.w - __half2float(hw));
    uint2 h;
    __half2 p0 = __halves2half2(hx, hy), p1 = __halves2half2(hz, hw);
    h.x = *(uint32_t*)&p0; h.y = *(uint32_t*)&p1;
    hi[i] = h;
    lo[i] = pack4h(l);
}

// ================= CSR build =================
__global__ void hist_k(const int* __restrict__ ei, int E, int* __restrict__ cnt) {
    int e = blockIdx.x * blockDim.x + threadIdx.x;
    if (e < E) atomicAdd(&cnt[ei[E + e]], 1);
}
__global__ void scan1_k(const int* __restrict__ cnt, int N, int* __restrict__ part,
                        int* __restrict__ bsum) {
    __shared__ int sh[1024];
    int t = threadIdx.x;
    int i = blockIdx.x * 1024 + t;
    sh[t] = (i < N) ? cnt[i] : 0;
    __syncthreads();
    for (int off = 1; off < 1024; off <<= 1) {
        int v = (t >= off) ? sh[t - off] : 0;
        __syncthreads();
        sh[t] += v;
        __syncthreads();
    }
    if (i < N) part[i] = sh[t];
    if (t == 1023) bsum[blockIdx.x] = sh[1023];
}
__global__ void scan2_k(int* __restrict__ bsum, int nb) {
    __shared__ int sh[128];
    int t = threadIdx.x;
    sh[t] = (t < nb) ? bsum[t] : 0;
    __syncthreads();
    for (int off = 1; off < 128; off <<= 1) {
        int v = (t >= off) ? sh[t - off] : 0;
        __syncthreads();
        sh[t] += v;
        __syncthreads();
    }
    if (t < nb) bsum[t] = sh[t];
}
__global__ void scan3_k(const int* __restrict__ part, const int* __restrict__ bsum,
                        int* __restrict__ rs, int N) {
    int i = blockIdx.x * blockDim.x + threadIdx.x;
    if (i < N) {
        int b = i >> 10;
        int off = (b > 0) ? bsum[b - 1] : 0;
        rs[i + 1] = part[i] + off;
    }
    if (i == 0) rs[0] = 0;
}
__global__ void fill_k(const int* __restrict__ ei, int E, const int* __restrict__ rs,
                       int* __restrict__ cur, int* __restrict__ csr) {
    int e = blockIdx.x * blockDim.x + threadIdx.x;
    if (e >= E) return;
    int s = ei[e], d = ei[E + e];
    int pos = atomicAdd(&cur[d], 1);
    csr[rs[d] + pos] = s;
}

// ================= fused dual CSR gather: mean(lrelu(feat)) -> fp16 =================
__global__ void gather2_k(const float* __restrict__ fA, const int* __restrict__ csrA,
                          const int* __restrict__ rsA, int NA, uint2* __restrict__ aggA,
                          const float* __restrict__ fB, const int* __restrict__ csrB,
                          const int* __restrict__ rsB, int NB, uint2* __restrict__ aggB) {
    int w = (blockIdx.x * blockDim.x + threadIdx.x) >> 5;
    if (w >= NA + NB) return;
    int lane = threadIdx.x & 31;
    const float* feat;
    const int* csr;
    const int* rs;
    uint2* agg;
    int node;
    if (w < NA) { feat = fA; csr = csrA; rs = rsA; agg = aggA; node = w; }
    else        { feat = fB; csr = csrB; rs = rsB; agg = aggB; node = w - NA; }
    int beg = rs[node], end = rs[node + 1];
    float4 a0 = make_float4(0.f, 0.f, 0.f, 0.f), a1 = a0, a2 = a0, a3 = a0;
    for (int e = beg; e < end; e++) {
        const float4* p = (const float4*)(feat + (size_t)csr[e] * DD);
        float4 v;
        v = lrelu4(p[lane]);      a0.x += v.x; a0.y += v.y; a0.z += v.z; a0.w += v.w;
        v = lrelu4(p[lane + 32]); a1.x += v.x; a1.y += v.y; a1.z += v.z; a1.w += v.w;
        v = lrelu4(p[lane + 64]); a2.x += v.x; a2.y += v.y; a2.z += v.z; a2.w += v.w;
        v = lrelu4(p[lane + 96]); a3.x += v.x; a3.y += v.y; a3.z += v.z; a3.w += v.w;
    }
    int deg = end - beg;
    float sc = 1.f / (float)(deg > 1 ? deg : 1);
    a0.x *= sc; a0.y *= sc; a0.z *= sc; a0.w *= sc;
    a1.x *= sc; a1.y *= sc; a1.z *= sc; a1.w *= sc;
    a2.x *= sc; a2.y *= sc; a2.z *= sc; a2.w *= sc;
    a3.x *= sc; a3.y *= sc; a3.z *= sc; a3.w *= sc;
    size_t rb = (size_t)node * (DD / 4);
    agg[rb + lane]      = pack4h(a0);
    agg[rb + lane + 32] = pack4h(a1);
    agg[rb + lane + 64] = pack4h(a2);
    agg[rb + lane + 96] = pack4h(a3);
}

// ================= bias precombination =================
__global__ void biascomb_k(const float* __restrict__ bn, const float* __restrict__ bs,
                           const float* __restrict__ bu, const float* __restrict__ Wu,
                           float* __restrict__ bp) {
    int j = blockIdx.x * blockDim.x + threadIdx.x;
    if (j >= DD) return;
    const float* WuT = Wu;
    const float* WuB = Wu + DD * DD;
    float acc = bu[j];
    for (int k = 0; k < DD; k++)
        acc += bn[k] * WuT[k * DD + j] + bs[k] * WuB[k * DD + j];
    bp[j] = acc;
}

// ================= batched fp32 512^3 precombine GEMM =================
struct PrePtrs { const float* A[8]; const float* Bm[8]; float* C[8]; };

__global__ __launch_bounds__(256, 2) void gemm_pre_k(PrePtrs p) {
    const float* A = p.A[blockIdx.z];
    const float* W = p.Bm[blockIdx.z];
    float* C = p.C[blockIdx.z];
    __shared__ float As[16][128];
    __shared__ float Bs[16][128];
    const int tid = threadIdx.x;
    const int tx = tid & 15, ty = tid >> 4;
    const int row0 = blockIdx.y * 128, col0 = blockIdx.x * 128;
    float acc[8][8];
#pragma unroll
    for (int i = 0; i < 8; i++)
#pragma unroll
        for (int j = 0; j < 8; j++) acc[i][j] = 0.f;
    const int lm = tid >> 1, lk = (tid & 1) * 8;
    const int wk = tid >> 4, wc = (tid & 15) * 8;
    for (int kk = 0; kk < 512; kk += 16) {
        const float* pA = A + (size_t)(row0 + lm) * 512 + kk + lk;
        float4 a0 = *(const float4*)pA, a1 = *(const float4*)(pA + 4);
        const float* pW = W + (size_t)(kk + wk) * 512 + col0 + wc;
        float4 w0 = *(const float4*)pW, w1 = *(const float4*)(pW + 4);
        As[lk + 0][lm] = a0.x; As[lk + 1][lm] = a0.y;
        As[lk + 2][lm] = a0.z; As[lk + 3][lm] = a0.w;
        As[lk + 4][lm] = a1.x; As[lk + 5][lm] = a1.y;
        As[lk + 6][lm] = a1.z; As[lk + 7][lm] = a1.w;
        *(float4*)&Bs[wk][wc] = w0;
        *(float4*)&Bs[wk][wc + 4] = w1;
        __syncthreads();
#pragma unroll
        for (int k = 0; k < 16; k++) {
            float ra[8], rb[8];
            *(float4*)&ra[0] = *(const float4*)&As[k][ty * 8];
            *(float4*)&ra[4] = *(const float4*)&As[k][ty * 8 + 4];
            *(float4*)&rb[0] = *(const float4*)&Bs[k][tx * 8];
            *(float4*)&rb[4] = *(const float4*)&Bs[k][tx * 8 + 4];
#pragma unroll
            for (int i = 0; i < 8; i++)
#pragma unroll
                for (int j = 0; j < 8; j++) acc[i][j] += ra[i] * rb[j];
        }
        __syncthreads();
    }
#pragma unroll
    for (int i = 0; i < 8; i++) {
        float* cp = C + (size_t)(row0 + ty * 8 + i) * 512 + col0 + tx * 8;
        *(float4*)cp = make_float4(acc[i][0], acc[i][1], acc[i][2], acc[i][3]);
        *(float4*)(cp + 4) = make_float4(acc[i][4], acc[i][5], acc[i][6], acc[i][7]);
    }
}

// ================= fp16 2-pass tensor-core GEMM (mma.sync), paired via blockIdx.z ==========
// C = A0@(W0h+W0l) + A1@(W1h+W1l) + bias.  A is plain fp16; W split exact (fp16 hi/lo).
// 128x128 tile, K chunk 32, 4-stage cp.async ring, 2 CTAs/SM.

#define APAD 40
#define BPAD 136
#define A_T (128 * APAD)
#define B_T (32 * BPAD)
#define STG (A_T + 2 * B_T)              // elems per stage (13,824)
#define NSTAGE 4
#define GEMM_SMEM (NSTAGE * STG * 2)     // 110,592 bytes
#define NST 32                            // 2 phases * (512/32)

__device__ __forceinline__ void cp16(uint32_t s, const void* g, int p16) {
    asm volatile("cp.async.cg.shared.global [%0], [%1], 16, %2;\n"
                 :: "r"(s), "l"(g), "r"(p16));
}

#define LDSM4(R, addr) \
    asm volatile("ldmatrix.sync.aligned.m8n8.x4.shared.b16 {%0,%1,%2,%3},[%4];\n" \
        : "=r"((R)[0]), "=r"((R)[1]), "=r"((R)[2]), "=r"((R)[3]) : "r"(addr))

#define LDSM4T(r0, r1, r2, r3, addr) \
    asm volatile("ldmatrix.sync.aligned.m8n8.x4.trans.shared.b16 {%0,%1,%2,%3},[%4];\n" \
        : "=r"(r0), "=r"(r1), "=r"(r2), "=r"(r3) : "r"(addr))

#define MMA16816(D, Af, Bf) \
    asm volatile("mma.sync.aligned.m16n8k16.row.col.f32.f16.f16.f32 " \
        "{%0,%1,%2,%3},{%4,%5,%6,%7},{%8,%9},{%0,%1,%2,%3};\n" \
        : "+f"((D)[0]), "+f"((D)[1]), "+f"((D)[2]), "+f"((D)[3]) \
        : "r"((Af)[0]), "r"((Af)[1]), "r"((Af)[2]), "r"((Af)[3]), \
          "r"((Bf)[0]), "r"((Bf)[1]))

struct G2 {
    const fp16 *A0[2], *A1[2];
    const fp16 *W0h[2], *W0l[2], *W1h[2], *W1l[2];
    const float *bias[2];
    float *C[2];
    uint32_t *Split[2];     // optional fp16(lrelu(C)) output, nullptr to skip
    int M[2];
};

__global__ __launch_bounds__(256, 2) void gemm_fp16_k(G2 g) {
    const int z = blockIdx.z;
    const fp16* A0 = g.A0[z];
    const fp16* A1 = g.A1[z];
    const fp16* W0h = g.W0h[z];
    const fp16* W0l = g.W0l[z];
    const fp16* W1h = g.W1h[z];
    const fp16* W1l = g.W1l[z];
    const float* bias = g.bias[z];
    float* C = g.C[z];
    uint32_t* Split = g.Split[z];
    const int M = g.M[z];

    extern __shared__ fp16 smdyn[];
    uint32_t smb = (uint32_t)__cvta_generic_to_shared(smdyn);
    const int tid = threadIdx.x;
    const int lane = tid & 31;
    const int wid = tid >> 5;
    const int warp_m = wid & 1, warp_n = wid >> 1;
    const int row0 = blockIdx.y * 128, col0 = blockIdx.x * 128;
    if (row0 >= M) return;

    float acc[16][4];
#pragma unroll
    for (int i = 0; i < 16; i++) { acc[i][0] = acc[i][1] = acc[i][2] = acc[i][3] = 0.f; }

    // loader mapping
    const int arow = tid >> 1, ac0 = (tid & 1) * 16;
    const int brow = tid >> 3, bc0 = (tid & 7) * 16;
    const int agrow = row0 + arow;
    const int apred = (agrow < M) ? 16 : 0;
    const size_t aoff = (size_t)(agrow < M ? agrow : 0) * DD;

    auto issue = [&](int s) {
        const int ph = s >> 4;              // 0 = (A0,W0), 1 = (A1,W1)
        const int k0 = (s & 15) * 32;       // K chunk within phase
        const int buf = s % NSTAGE;
        const fp16* A = ph ? A1 : A0;
        const fp16* Wh = ph ? W1h : W0h;
        const fp16* Wl = ph ? W1l : W0l;
        uint32_t base = smb + buf * (STG * 2);
        uint32_t sa = base + (arow * APAD + ac0) * 2;
        const fp16* ga = A + aoff + k0 + ac0;
        cp16(sa, ga, apred);
        cp16(sa + 16, ga + 8, apred);
        uint32_t sb = base + (A_T + brow * BPAD + bc0) * 2;
        const fp16* gb = Wh + (size_t)(k0 + brow) * DD + col0 + bc0;
        cp16(sb, gb, 16);
        cp16(sb + 16, gb + 8, 16);
        uint32_t sbl = base + ((A_T + B_T) + brow * BPAD + bc0) * 2;
        const fp16* gbl = Wl + (size_t)(k0 + brow) * DD + col0 + bc0;
        cp16(sbl, gbl, 16);
        cp16(sbl + 16, gbl + 8, 16);
        asm volatile("cp.async.commit_group;\n");
    };

    const int am = warp_m * 64 + (lane & 15);
    const int akoff = (lane >> 4) << 3;           // 0 or 8
    const int bk = lane & 15;
    const int bn = warp_n * 32 + ((lane & 16) ? 8 : 0);

    issue(0); issue(1); issue(2); issue(3);

#pragma unroll 1
    for (int s = 0; s < NST; s++) {
        if (s < NST - 3)       asm volatile("cp.async.wait_group 3;\n" ::: "memory");
        else if (s == NST - 3) asm volatile("cp.async.wait_group 2;\n" ::: "memory");
        else if (s == NST - 2) asm volatile("cp.async.wait_group 1;\n" ::: "memory");
        else                   asm volatile("cp.async.wait_group 0;\n" ::: "memory");
        __syncthreads();

        const int buf = s % NSTAGE;
        uint32_t base = smb + buf * (STG * 2);
        uint32_t Ab = base;
        uint32_t Bb = base + A_T * 2;
        uint32_t Blb = base + (A_T + B_T) * 2;
#pragma unroll
        for (int kk = 0; kk < 32; kk += 16) {
            uint32_t bh[4][2], bl[4][2];
#pragma unroll
            for (int pr = 0; pr < 2; pr++) {
                uint32_t off = ((kk + bk) * BPAD + bn + pr * 16) * 2;
                uint32_t r0, r1, r2, r3;
                LDSM4T(r0, r1, r2, r3, Bb + off);
                bh[2 * pr][0] = r0; bh[2 * pr][1] = r1;
                bh[2 * pr + 1][0] = r2; bh[2 * pr + 1][1] = r3;
                LDSM4T(r0, r1, r2, r3, Blb + off);
                bl[2 * pr][0] = r0; bl[2 * pr][1] = r1;
                bl[2 * pr + 1][0] = r2; bl[2 * pr + 1][1] = r3;
            }
#pragma unroll
            for (int mt = 0; mt < 4; mt++) {
                uint32_t ah[4];
                uint32_t off = ((am + mt * 16) * APAD + kk + akoff) * 2;
                LDSM4(ah, Ab + off);
#pragma unroll
                for (int nt = 0; nt < 4; nt++) {
                    MMA16816(acc[mt * 4 + nt], ah, bh[nt]);
                    MMA16816(acc[mt * 4 + nt], ah, bl[nt]);
                }
            }
        }
        __syncthreads();
        if (s + NSTAGE < NST) issue(s + NSTAGE);
    }

    // epilogue
    const int er = row0 + warp_m * 64 + (lane >> 2);
    const int ec = col0 + warp_n * 32 + (lane & 3) * 2;
#pragma unroll
    for (int mt = 0; mt < 4; mt++) {
#pragma unroll
        for (int nt = 0; nt < 4; nt++) {
            int c = ec + nt * 8;
            float b0 = bias[c], b1 = bias[c + 1];
#pragma unroll
            for (int hh = 0; hh < 2; hh++) {
                int r = er + mt * 16 + hh * 8;
                if (r < M) {
                    float v0 = acc[mt * 4 + nt][2 * hh] + b0;
                    float v1 = acc[mt * 4 + nt][2 * hh + 1] + b1;
                    *(float2*)(C + (size_t)r * DD + c) = make_float2(v0, v1);
                    if (Split != nullptr) {
                        float w0 = v0 > 0.f ? v0 : 0.01f * v0;
                        float w1 = v1 > 0.f ? v1 : 0.01f * v1;
                        __half2 hp = __floats2half2_rn(w0, w1);
                        Split[((size_t)r * DD + c) >> 1] = *(uint32_t*)&hp;
                    }
                }
            }
        }
    }
}

// ================= host orchestration =================
static void build_csr(const int* ei, int E, int N, int* cnt, int* part, int* bsum,
                      int* cur, int* rs, int* csr) {
    cudaMemsetAsync(cnt, 0, (size_t)N * sizeof(int));
    hist_k<<<(E + 255) / 256, 256>>>(ei, E, cnt);
    int nb = (N + 1023) / 1024;
    scan1_k<<<nb, 1024>>>(cnt, N, part, bsum);
    scan2_k<<<1, 128>>>(bsum, nb);
    scan3_k<<<nb, 1024>>>(part, bsum, rs, N);
    cudaMemsetAsync(cur, 0, (size_t)N * sizeof(int));
    fill_k<<<(E + 255) / 256, 256>>>(ei, E, rs, cur, csr);
}

extern "C" void kernel_launch(void* const* d_in, const int* in_sizes, int n_in,
                              void* d_out, int out_size) {
    const float* x0 = (const float*)d_in[0];
    const float* x1 = (const float*)d_in[1];
    const int* ei01 = (const int*)d_in[2];
    const int* ei10 = (const int*)d_in[3];
    const int N0 = in_sizes[0] / DD;
    const int N1 = in_sizes[1] / DD;
    const int E01 = in_sizes[2] / 2;
    const int E10 = in_sizes[3] / 2;

    float *o0, *o1, *Wp, *bp;
    fp16 *h0, *h1, *s0, *s1, *agga, *aggb, *Wph, *Wpl;
    int *csr01, *csr10, *rs01, *rs10, *cnt, *part, *bsum, *cur;
    cudaGetSymbolAddress((void**)&o0, g_o0);
    cudaGetSymbolAddress((void**)&o1, g_o1);
    cudaGetSymbolAddress((void**)&h0, g_h0);
    cudaGetSymbolAddress((void**)&h1, g_h1);
    cudaGetSymbolAddress((void**)&s0, g_s0);
    cudaGetSymbolAddress((void**)&s1, g_s1);
    cudaGetSymbolAddress((void**)&agga, g_agga);
    cudaGetSymbolAddress((void**)&aggb, g_aggb);
    cudaGetSymbolAddress((void**)&Wp, g_Wp);
    cudaGetSymbolAddress((void**)&Wph, g_Wph);
    cudaGetSymbolAddress((void**)&Wpl, g_Wpl);
    cudaGetSymbolAddress((void**)&bp, g_bp);
    cudaGetSymbolAddress((void**)&csr01, g_csr01);
    cudaGetSymbolAddress((void**)&csr10, g_csr10);
    cudaGetSymbolAddress((void**)&rs01, g_rs01);
    cudaGetSymbolAddress((void**)&rs10, g_rs10);
    cudaGetSymbolAddress((void**)&cnt, g_cnt);
    cudaGetSymbolAddress((void**)&part, g_part);
    cudaGetSymbolAddress((void**)&bsum, g_bsum);
    cudaGetSymbolAddress((void**)&cur, g_cur);

    cudaFuncSetAttribute(gemm_fp16_k, cudaFuncAttributeMaxDynamicSharedMemorySize,
                         GEMM_SMEM);

    // ---- CSR build ----
    build_csr(ei01, E01, N1, cnt, part, bsum, cur, rs01, csr01);
    build_csr(ei10, E10, N0, cnt, part, bsum, cur, rs10, csr10);

    // ---- precombine weights: Wp[2s]=Wn@WuT, Wp[2s+1]=Ws@WuB ----
    PrePtrs pp;
    for (int s = 0; s < 4; s++) {
        const float* Wn = (const float*)d_in[4 + 6 * s + 0];
        const float* bn = (const float*)d_in[4 + 6 * s + 1];
        const float* Ws_ = (const float*)d_in[4 + 6 * s + 2];
        const float* bs = (const float*)d_in[4 + 6 * s + 3];
        const float* Wu = (const float*)d_in[4 + 6 * s + 4];
        const float* bu = (const float*)d_in[4 + 6 * s + 5];
        pp.A[2 * s] = Wn;      pp.Bm[2 * s] = Wu;
        pp.C[2 * s] = Wp + (size_t)(2 * s) * DD * DD;
        pp.A[2 * s + 1] = Ws_; pp.Bm[2 * s + 1] = Wu + DD * DD;
        pp.C[2 * s + 1] = Wp + (size_t)(2 * s + 1) * DD * DD;
        biascomb_k<<<2, 256>>>(bn, bs, bu, Wu, bp + s * DD);
    }
    {
        dim3 g(4, 4, 8);
        gemm_pre_k<<<g, 256>>>(pp);
    }
    {
        int n4 = 8 * DD * DD / 4;
        wconv_k<<<(n4 + 255) / 256, 256>>>((const float4*)Wp, (uint2*)Wph, (uint2*)Wpl, n4);
    }

    const int n40 = N0 * (DD / 4);
    const int n41 = N1 * (DD / 4);

    // ---- layer 1: self fp16 + fused dual gather ----
    hhalf_k<<<(n40 + 255) / 256, 256>>>((const float4*)x0, (uint2*)h0, n40);
    hhalf_k<<<(n41 + 255) / 256, 256>>>((const float4*)x1, (uint2*)h1, n41);
    {
        int totw = N1 + N0;
        gather2_k<<<(totw + 7) / 8, 256>>>(x0, csr01, rs01, N1, (uint2*)agga,
                                           x1, csr10, rs10, N0, (uint2*)aggb);
    }
    // ---- layer 1 fused GEMM pair ----
    {
        G2 g;
        // z=0: dst type 1 -> o1 (+ s1 split)
        g.A0[0] = agga; g.A1[0] = h1;
        g.W0h[0] = Wph + (size_t)0 * DD * DD; g.W0l[0] = Wpl + (size_t)0 * DD * DD;
        g.W1h[0] = Wph + (size_t)1 * DD * DD; g.W1l[0] = Wpl + (size_t)1 * DD * DD;
        g.bias[0] = bp + 0 * DD; g.C[0] = o1; g.Split[0] = (uint32_t*)s1; g.M[0] = N1;
        // z=1: dst type 0 -> o0 (+ s0 split)
        g.A0[1] = aggb; g.A1[1] = h0;
        g.W0h[1] = Wph + (size_t)2 * DD * DD; g.W0l[1] = Wpl + (size_t)2 * DD * DD;
        g.W1h[1] = Wph + (size_t)3 * DD * DD; g.W1l[1] = Wpl + (size_t)3 * DD * DD;
        g.bias[1] = bp + 1 * DD; g.C[1] = o0; g.Split[1] = (uint32_t*)s0; g.M[1] = N0;
        int mmax = (N0 > N1 ? N0 : N1);
        dim3 gr(4, (mmax + 127) / 128, 2);
        gemm_fp16_k<<<gr, 256, GEMM_SMEM>>>(g);
    }

    // ---- layer 2: fused dual gather on o0/o1 ----
    {
        int totw = N1 + N0;
        gather2_k<<<(totw + 7) / 8, 256>>>(o0, csr01, rs01, N1, (uint2*)agga,
                                           o1, csr10, rs10, N0, (uint2*)aggb);
    }
    // ---- layer 2 fused GEMM pair -> outputs ----
    {
        float* out0 = (float*)d_out;
        float* out1 = out0 + (size_t)N0 * DD;
        G2 g;
        g.A0[0] = agga; g.A1[0] = s1;
        g.W0h[0] = Wph + (size_t)4 * DD * DD; g.W0l[0] = Wpl + (size_t)4 * DD * DD;
        g.W1h[0] = Wph + (size_t)5 * DD * DD; g.W1l[0] = Wpl + (size_t)5 * DD * DD;
        g.bias[0] = bp + 2 * DD; g.C[0] = out1; g.Split[0] = nullptr; g.M[0] = N1;
        g.A0[1] = aggb; g.A1[1] = s0;
        g.W0h[1] = Wph + (size_t)6 * DD * DD; g.W0l[1] = Wpl + (size_t)6 * DD * DD;
        g.W1h[1] = Wph + (size_t)7 * DD * DD; g.W1l[1] = Wpl + (size_t)7 * DD * DD;
        g.bias[1] = bp + 3 * DD; g.C[1] = out0; g.Split[1] = nullptr; g.M[1] = N0;
        int mmax = (N0 > N1 ? N0 : N1);
        dim3 gr(4, (mmax + 127) / 128, 2);
        gemm_fp16_k<<<gr, 256, GEMM_SMEM>>>(g);
    }
}

// round 13
// speedup vs baseline: 6.1722x; 1.5004x over previous
#include <cuda_runtime.h>
#include <cuda_fp16.h>
#include <cstdint>
#include <cstddef>

#define DD 512
#define NNODE 100000
#define EMAX 1000000
typedef __half fp16;

// ---- static device scratch (allocation-free rule) ----
__device__ fp16  g_h0[NNODE * DD];      // fp16(lrelu(x0))
__device__ fp16  g_h1[NNODE * DD];
__device__ fp16  g_s0[NNODE * DD];      // fp16(lrelu(o0))
__device__ fp16  g_s1[NNODE * DD];
__device__ fp16  g_agga[NNODE * DD];    // agg for dst type 1
__device__ fp16  g_aggb[NNODE * DD];    // agg for dst type 0
__device__ fp16  g_Wph[8 * DD * DD];    // precombined fp16 weights
__device__ float g_bp[4 * DD];
__device__ int   g_csr01[EMAX];
__device__ int   g_csr10[EMAX];
__device__ int   g_rs01[NNODE + 1];
__device__ int   g_rs10[NNODE + 1];
__device__ int   g_cnt[NNODE];
__device__ int   g_part[NNODE];
__device__ int   g_bsum[256];
__device__ int   g_cur[NNODE];

// ================= helpers =================
__device__ __forceinline__ float4 lrelu4(float4 v) {
    v.x = v.x > 0.f ? v.x : 0.01f * v.x;
    v.y = v.y > 0.f ? v.y : 0.01f * v.y;
    v.z = v.z > 0.f ? v.z : 0.01f * v.z;
    v.w = v.w > 0.f ? v.w : 0.01f * v.w;
    return v;
}
__device__ __forceinline__ uint2 pack4h(float4 v) {
    __half2 a = __floats2half2_rn(v.x, v.y);
    __half2 b = __floats2half2_rn(v.z, v.w);
    uint2 r;
    r.x = *(uint32_t*)&a;
    r.y = *(uint32_t*)&b;
    return r;
}

// ================= elementwise: lrelu -> fp16 =================
__global__ void hhalf_k(const float4* __restrict__ in, uint2* __restrict__ out, int n4) {
    int i = blockIdx.x * blockDim.x + threadIdx.x;
    if (i >= n4) return;
    out[i] = pack4h(lrelu4(in[i]));
}

// ================= CSR build =================
__global__ void hist_k(const int* __restrict__ ei, int E, int* __restrict__ cnt) {
    int e = blockIdx.x * blockDim.x + threadIdx.x;
    if (e < E) atomicAdd(&cnt[ei[E + e]], 1);
}
__global__ void scan1_k(const int* __restrict__ cnt, int N, int* __restrict__ part,
                        int* __restrict__ bsum) {
    __shared__ int sh[1024];
    int t = threadIdx.x;
    int i = blockIdx.x * 1024 + t;
    sh[t] = (i < N) ? cnt[i] : 0;
    __syncthreads();
    for (int off = 1; off < 1024; off <<= 1) {
        int v = (t >= off) ? sh[t - off] : 0;
        __syncthreads();
        sh[t] += v;
        __syncthreads();
    }
    if (i < N) part[i] = sh[t];
    if (t == 1023) bsum[blockIdx.x] = sh[1023];
}
__global__ void scan2_k(int* __restrict__ bsum, int nb) {
    __shared__ int sh[128];
    int t = threadIdx.x;
    sh[t] = (t < nb) ? bsum[t] : 0;
    __syncthreads();
    for (int off = 1; off < 128; off <<= 1) {
        int v = (t >= off) ? sh[t - off] : 0;
        __syncthreads();
        sh[t] += v;
        __syncthreads();
    }
    if (t < nb) bsum[t] = sh[t];
}
__global__ void scan3_k(const int* __restrict__ part, const int* __restrict__ bsum,
                        int* __restrict__ rs, int N) {
    int i = blockIdx.x * blockDim.x + threadIdx.x;
    if (i < N) {
        int b = i >> 10;
        int off = (b > 0) ? bsum[b - 1] : 0;
        rs[i + 1] = part[i] + off;
    }
    if (i == 0) rs[0] = 0;
}
__global__ void fill_k(const int* __restrict__ ei, int E, const int* __restrict__ rs,
                       int* __restrict__ cur, int* __restrict__ csr) {
    int e = blockIdx.x * blockDim.x + threadIdx.x;
    if (e >= E) return;
    int s = ei[e], d = ei[E + e];
    int pos = atomicAdd(&cur[d], 1);
    csr[rs[d] + pos] = s;
}

// ================= fused dual CSR gather over fp16 features -> fp16 mean ============
// feats are already lrelu'd fp16. Row = 512 fp16 = 64 uint4; lane handles 2 uint4.
__global__ void gather2h_k(const fp16* __restrict__ fA, const int* __restrict__ csrA,
                           const int* __restrict__ rsA, int NA, uint4* __restrict__ aggA,
                           const fp16* __restrict__ fB, const int* __restrict__ csrB,
                           const int* __restrict__ rsB, int NB, uint4* __restrict__ aggB) {
    int w = (blockIdx.x * blockDim.x + threadIdx.x) >> 5;
    if (w >= NA + NB) return;
    int lane = threadIdx.x & 31;
    const fp16* feat;
    const int* csr;
    const int* rs;
    uint4* agg;
    int node;
    if (w < NA) { feat = fA; csr = csrA; rs = rsA; agg = aggA; node = w; }
    else        { feat = fB; csr = csrB; rs = rsB; agg = aggB; node = w - NA; }
    int beg = rs[node], end = rs[node + 1];
    float a[16];
#pragma unroll
    for (int i = 0; i < 16; i++) a[i] = 0.f;
    for (int e = beg; e < end; e++) {
        const uint4* p = (const uint4*)(feat + (size_t)csr[e] * DD);
        uint4 v0 = p[lane];
        uint4 v1 = p[lane + 32];
        const uint32_t* u0 = &v0.x;
        const uint32_t* u1 = &v1.x;
#pragma unroll
        for (int j = 0; j < 4; j++) {
            float2 f0 = __half22float2(*(const __half2*)&u0[j]);
            float2 f1 = __half22float2(*(const __half2*)&u1[j]);
            a[2 * j] += f0.x;     a[2 * j + 1] += f0.y;
            a[8 + 2 * j] += f1.x; a[8 + 2 * j + 1] += f1.y;
        }
    }
    int deg = end - beg;
    float sc = 1.f / (float)(deg > 1 ? deg : 1);
    uint4 o0, o1;
    uint32_t* q0 = &o0.x;
    uint32_t* q1 = &o1.x;
#pragma unroll
    for (int j = 0; j < 4; j++) {
        __half2 h0 = __floats2half2_rn(a[2 * j] * sc, a[2 * j + 1] * sc);
        __half2 h1 = __floats2half2_rn(a[8 + 2 * j] * sc, a[8 + 2 * j + 1] * sc);
        q0[j] = *(uint32_t*)&h0;
        q1[j] = *(uint32_t*)&h1;
    }
    size_t rb = (size_t)node * (DD / 8);
    agg[rb + lane] = o0;
    agg[rb + lane + 32] = o1;
}

// ================= bias precombination =================
__global__ void biascomb_k(const float* __restrict__ bn, const float* __restrict__ bs,
                           const float* __restrict__ bu, const float* __restrict__ Wu,
                           float* __restrict__ bp) {
    int j = blockIdx.x * blockDim.x + threadIdx.x;
    if (j >= DD) return;
    const float* WuT = Wu;
    const float* WuB = Wu + DD * DD;
    float acc = bu[j];
    for (int k = 0; k < DD; k++)
        acc += bn[k] * WuT[k * DD + j] + bs[k] * WuB[k * DD + j];
    bp[j] = acc;
}

// ================= batched fp32 512^3 precombine GEMM -> fp16 out =================
struct PrePtrs { const float* A[8]; const float* Bm[8]; fp16* C[8]; };

__global__ __launch_bounds__(256, 2) void gemm_pre_k(PrePtrs p) {
    const float* A = p.A[blockIdx.z];
    const float* W = p.Bm[blockIdx.z];
    fp16* C = p.C[blockIdx.z];
    __shared__ float As[16][128];
    __shared__ float Bs[16][128];
    const int tid = threadIdx.x;
    const int tx = tid & 15, ty = tid >> 4;
    const int row0 = blockIdx.y * 128, col0 = blockIdx.x * 128;
    float acc[8][8];
#pragma unroll
    for (int i = 0; i < 8; i++)
#pragma unroll
        for (int j = 0; j < 8; j++) acc[i][j] = 0.f;
    const int lm = tid >> 1, lk = (tid & 1) * 8;
    const int wk = tid >> 4, wc = (tid & 15) * 8;
    for (int kk = 0; kk < 512; kk += 16) {
        const float* pA = A + (size_t)(row0 + lm) * 512 + kk + lk;
        float4 a0 = *(const float4*)pA, a1 = *(const float4*)(pA + 4);
        const float* pW = W + (size_t)(kk + wk) * 512 + col0 + wc;
        float4 w0 = *(const float4*)pW, w1 = *(const float4*)(pW + 4);
        As[lk + 0][lm] = a0.x; As[lk + 1][lm] = a0.y;
        As[lk + 2][lm] = a0.z; As[lk + 3][lm] = a0.w;
        As[lk + 4][lm] = a1.x; As[lk + 5][lm] = a1.y;
        As[lk + 6][lm] = a1.z; As[lk + 7][lm] = a1.w;
        *(float4*)&Bs[wk][wc] = w0;
        *(float4*)&Bs[wk][wc + 4] = w1;
        __syncthreads();
#pragma unroll
        for (int k = 0; k < 16; k++) {
            float ra[8], rb[8];
            *(float4*)&ra[0] = *(const float4*)&As[k][ty * 8];
            *(float4*)&ra[4] = *(const float4*)&As[k][ty * 8 + 4];
            *(float4*)&rb[0] = *(const float4*)&Bs[k][tx * 8];
            *(float4*)&rb[4] = *(const float4*)&Bs[k][tx * 8 + 4];
#pragma unroll
            for (int i = 0; i < 8; i++)
#pragma unroll
                for (int j = 0; j < 8; j++) acc[i][j] += ra[i] * rb[j];
        }
        __syncthreads();
    }
#pragma unroll
    for (int i = 0; i < 8; i++) {
        fp16* cp = C + (size_t)(row0 + ty * 8 + i) * 512 + col0 + tx * 8;
        uint4 o;
        uint32_t* q = &o.x;
#pragma unroll
        for (int j = 0; j < 4; j++) {
            __half2 h = __floats2half2_rn(acc[i][2 * j], acc[i][2 * j + 1]);
            q[j] = *(uint32_t*)&h;
        }
        *(uint4*)cp = o;
    }
}

// ================= fp16 single-pass tensor-core GEMM, paired via blockIdx.z ==========
// C = A0@W0 + A1@W1 + bias.  All operands plain fp16, fp32 accum.
// 128x128 tile, K chunk 32, 4-stage cp.async ring, 2 CTAs/SM.

#define APAD 40
#define BPAD 136
#define A_T (128 * APAD)
#define B_T (32 * BPAD)
#define STG (A_T + B_T)                  // elems per stage (9,472)
#define NSTAGE 4
#define GEMM_SMEM (NSTAGE * STG * 2)     // 75,776 bytes
#define NST 32                            // 2 phases * (512/32)

__device__ __forceinline__ void cp16(uint32_t s, const void* g, int p16) {
    asm volatile("cp.async.cg.shared.global [%0], [%1], 16, %2;\n"
                 :: "r"(s), "l"(g), "r"(p16));
}

#define LDSM4(R, addr) \
    asm volatile("ldmatrix.sync.aligned.m8n8.x4.shared.b16 {%0,%1,%2,%3},[%4];\n" \
        : "=r"((R)[0]), "=r"((R)[1]), "=r"((R)[2]), "=r"((R)[3]) : "r"(addr))

#define LDSM4T(r0, r1, r2, r3, addr) \
    asm volatile("ldmatrix.sync.aligned.m8n8.x4.trans.shared.b16 {%0,%1,%2,%3},[%4];\n" \
        : "=r"(r0), "=r"(r1), "=r"(r2), "=r"(r3) : "r"(addr))

#define MMA16816(D, Af, Bf) \
    asm volatile("mma.sync.aligned.m16n8k16.row.col.f32.f16.f16.f32 " \
        "{%0,%1,%2,%3},{%4,%5,%6,%7},{%8,%9},{%0,%1,%2,%3};\n" \
        : "+f"((D)[0]), "+f"((D)[1]), "+f"((D)[2]), "+f"((D)[3]) \
        : "r"((Af)[0]), "r"((Af)[1]), "r"((Af)[2]), "r"((Af)[3]), \
          "r"((Bf)[0]), "r"((Bf)[1]))

struct G2 {
    const fp16 *A0[2], *A1[2];
    const fp16 *W0[2], *W1[2];
    const float *bias[2];
    float *C[2];            // optional fp32 out (nullptr to skip)
    uint32_t *Split[2];     // optional fp16(lrelu(C)) out (nullptr to skip)
    int M[2];
};

__global__ __launch_bounds__(256, 2) void gemm_fp16_k(G2 g) {
    const int z = blockIdx.z;
    const fp16* A0 = g.A0[z];
    const fp16* A1 = g.A1[z];
    const fp16* W0 = g.W0[z];
    const fp16* W1 = g.W1[z];
    const float* bias = g.bias[z];
    float* C = g.C[z];
    uint32_t* Split = g.Split[z];
    const int M = g.M[z];

    extern __shared__ fp16 smdyn[];
    uint32_t smb = (uint32_t)__cvta_generic_to_shared(smdyn);
    const int tid = threadIdx.x;
    const int lane = tid & 31;
    const int wid = tid >> 5;
    const int warp_m = wid & 1, warp_n = wid >> 1;
    const int row0 = blockIdx.y * 128, col0 = blockIdx.x * 128;
    if (row0 >= M) return;

    float acc[16][4];
#pragma unroll
    for (int i = 0; i < 16; i++) { acc[i][0] = acc[i][1] = acc[i][2] = acc[i][3] = 0.f; }

    // loader mapping
    const int arow = tid >> 1, ac0 = (tid & 1) * 16;
    const int brow = tid >> 3, bc0 = (tid & 7) * 16;
    const int agrow = row0 + arow;
    const int apred = (agrow < M) ? 16 : 0;
    const size_t aoff = (size_t)(agrow < M ? agrow : 0) * DD;

    auto issue = [&](int s) {
        const int ph = s >> 4;              // 0 = (A0,W0), 1 = (A1,W1)
        const int k0 = (s & 15) * 32;       // K chunk within phase
        const int buf = s % NSTAGE;
        const fp16* A = ph ? A1 : A0;
        const fp16* W = ph ? W1 : W0;
        uint32_t base = smb + buf * (STG * 2);
        uint32_t sa = base + (arow * APAD + ac0) * 2;
        const fp16* ga = A + aoff + k0 + ac0;
        cp16(sa, ga, apred);
        cp16(sa + 16, ga + 8, apred);
        uint32_t sb = base + (A_T + brow * BPAD + bc0) * 2;
        const fp16* gb = W + (size_t)(k0 + brow) * DD + col0 + bc0;
        cp16(sb, gb, 16);
        cp16(sb + 16, gb + 8, 16);
        asm volatile("cp.async.commit_group;\n");
    };

    const int am = warp_m * 64 + (lane & 15);
    const int akoff = (lane >> 4) << 3;           // 0 or 8
    const int bk = lane & 15;
    const int bn = warp_n * 32 + ((lane & 16) ? 8 : 0);

    issue(0); issue(1); issue(2); issue(3);

#pragma unroll 1
    for (int s = 0; s < NST; s++) {
        if (s < NST - 3)       asm volatile("cp.async.wait_group 3;\n" ::: "memory");
        else if (s == NST - 3) asm volatile("cp.async.wait_group 2;\n" ::: "memory");
        else if (s == NST - 2) asm volatile("cp.async.wait_group 1;\n" ::: "memory");
        else                   asm volatile("cp.async.wait_group 0;\n" ::: "memory");
        __syncthreads();

        const int buf = s % NSTAGE;
        uint32_t base = smb + buf * (STG * 2);
        uint32_t Ab = base;
        uint32_t Bb = base + A_T * 2;
#pragma unroll
        for (int kk = 0; kk < 32; kk += 16) {
            uint32_t bh[4][2];
#pragma unroll
            for (int pr = 0; pr < 2; pr++) {
                uint32_t off = ((kk + bk) * BPAD + bn + pr * 16) * 2;
                uint32_t r0, r1, r2, r3;
                LDSM4T(r0, r1, r2, r3, Bb + off);
                bh[2 * pr][0] = r0; bh[2 * pr][1] = r1;
                bh[2 * pr + 1][0] = r2; bh[2 * pr + 1][1] = r3;
            }
#pragma unroll
            for (int mt = 0; mt < 4; mt++) {
                uint32_t ah[4];
                uint32_t off = ((am + mt * 16) * APAD + kk + akoff) * 2;
                LDSM4(ah, Ab + off);
#pragma unroll
                for (int nt = 0; nt < 4; nt++) {
                    MMA16816(acc[mt * 4 + nt], ah, bh[nt]);
                }
            }
        }
        __syncthreads();
        if (s + NSTAGE < NST) issue(s + NSTAGE);
    }

    // epilogue
    const int er = row0 + warp_m * 64 + (lane >> 2);
    const int ec = col0 + warp_n * 32 + (lane & 3) * 2;
#pragma unroll
    for (int mt = 0; mt < 4; mt++) {
#pragma unroll
        for (int nt = 0; nt < 4; nt++) {
            int c = ec + nt * 8;
            float b0 = bias[c], b1 = bias[c + 1];
#pragma unroll
            for (int hh = 0; hh < 2; hh++) {
                int r = er + mt * 16 + hh * 8;
                if (r < M) {
                    float v0 = acc[mt * 4 + nt][2 * hh] + b0;
                    float v1 = acc[mt * 4 + nt][2 * hh + 1] + b1;
                    if (C != nullptr)
                        *(float2*)(C + (size_t)r * DD + c) = make_float2(v0, v1);
                    if (Split != nullptr) {
                        float w0 = v0 > 0.f ? v0 : 0.01f * v0;
                        float w1 = v1 > 0.f ? v1 : 0.01f * v1;
                        __half2 hp = __floats2half2_rn(w0, w1);
                        Split[((size_t)r * DD + c) >> 1] = *(uint32_t*)&hp;
                    }
                }
            }
        }
    }
}

// ================= host orchestration =================
static void build_csr(const int* ei, int E, int N, int* cnt, int* part, int* bsum,
                      int* cur, int* rs, int* csr) {
    cudaMemsetAsync(cnt, 0, (size_t)N * sizeof(int));
    hist_k<<<(E + 255) / 256, 256>>>(ei, E, cnt);
    int nb = (N + 1023) / 1024;
    scan1_k<<<nb, 1024>>>(cnt, N, part, bsum);
    scan2_k<<<1, 128>>>(bsum, nb);
    scan3_k<<<nb, 1024>>>(part, bsum, rs, N);
    cudaMemsetAsync(cur, 0, (size_t)N * sizeof(int));
    fill_k<<<(E + 255) / 256, 256>>>(ei, E, rs, cur, csr);
}

extern "C" void kernel_launch(void* const* d_in, const int* in_sizes, int n_in,
                              void* d_out, int out_size) {
    const float* x0 = (const float*)d_in[0];
    const float* x1 = (const float*)d_in[1];
    const int* ei01 = (const int*)d_in[2];
    const int* ei10 = (const int*)d_in[3];
    const int N0 = in_sizes[0] / DD;
    const int N1 = in_sizes[1] / DD;
    const int E01 = in_sizes[2] / 2;
    const int E10 = in_sizes[3] / 2;

    float *bp;
    fp16 *h0, *h1, *s0, *s1, *agga, *aggb, *Wph;
    int *csr01, *csr10, *rs01, *rs10, *cnt, *part, *bsum, *cur;
    cudaGetSymbolAddress((void**)&h0, g_h0);
    cudaGetSymbolAddress((void**)&h1, g_h1);
    cudaGetSymbolAddress((void**)&s0, g_s0);
    cudaGetSymbolAddress((void**)&s1, g_s1);
    cudaGetSymbolAddress((void**)&agga, g_agga);
    cudaGetSymbolAddress((void**)&aggb, g_aggb);
    cudaGetSymbolAddress((void**)&Wph, g_Wph);
    cudaGetSymbolAddress((void**)&bp, g_bp);
    cudaGetSymbolAddress((void**)&csr01, g_csr01);
    cudaGetSymbolAddress((void**)&csr10, g_csr10);
    cudaGetSymbolAddress((void**)&rs01, g_rs01);
    cudaGetSymbolAddress((void**)&rs10, g_rs10);
    cudaGetSymbolAddress((void**)&cnt, g_cnt);
    cudaGetSymbolAddress((void**)&part, g_part);
    cudaGetSymbolAddress((void**)&bsum, g_bsum);
    cudaGetSymbolAddress((void**)&cur, g_cur);

    cudaFuncSetAttribute(gemm_fp16_k, cudaFuncAttributeMaxDynamicSharedMemorySize,
                         GEMM_SMEM);

    // ---- CSR build ----
    build_csr(ei01, E01, N1, cnt, part, bsum, cur, rs01, csr01);
    build_csr(ei10, E10, N0, cnt, part, bsum, cur, rs10, csr10);

    // ---- precombine weights (fp16 out): Wph[2s]=Wn@WuT, Wph[2s+1]=Ws@WuB ----
    PrePtrs pp;
    for (int s = 0; s < 4; s++) {
        const float* Wn = (const float*)d_in[4 + 6 * s + 0];
        const float* bn = (const float*)d_in[4 + 6 * s + 1];
        const float* Ws_ = (const float*)d_in[4 + 6 * s + 2];
        const float* bs = (const float*)d_in[4 + 6 * s + 3];
        const float* Wu = (const float*)d_in[4 + 6 * s + 4];
        const float* bu = (const float*)d_in[4 + 6 * s + 5];
        pp.A[2 * s] = Wn;      pp.Bm[2 * s] = Wu;
        pp.C[2 * s] = Wph + (size_t)(2 * s) * DD * DD;
        pp.A[2 * s + 1] = Ws_; pp.Bm[2 * s + 1] = Wu + DD * DD;
        pp.C[2 * s + 1] = Wph + (size_t)(2 * s + 1) * DD * DD;
        biascomb_k<<<2, 256>>>(bn, bs, bu, Wu, bp + s * DD);
    }
    {
        dim3 g(4, 4, 8);
        gemm_pre_k<<<g, 256>>>(pp);
    }

    const int n40 = N0 * (DD / 4);
    const int n41 = N1 * (DD / 4);

    // ---- layer 1: self fp16 + fused dual gather over fp16 feats ----
    hhalf_k<<<(n40 + 255) / 256, 256>>>((const float4*)x0, (uint2*)h0, n40);
    hhalf_k<<<(n41 + 255) / 256, 256>>>((const float4*)x1, (uint2*)h1, n41);
    {
        int totw = N1 + N0;
        gather2h_k<<<(totw + 7) / 8, 256>>>(h0, csr01, rs01, N1, (uint4*)agga,
                                            h1, csr10, rs10, N0, (uint4*)aggb);
    }
    // ---- layer 1 fused GEMM pair (fp32 C skipped; fp16 splits only) ----
    {
        G2 g;
        g.A0[0] = agga; g.A1[0] = h1;
        g.W0[0] = Wph + (size_t)0 * DD * DD;
        g.W1[0] = Wph + (size_t)1 * DD * DD;
        g.bias[0] = bp + 0 * DD; g.C[0] = nullptr; g.Split[0] = (uint32_t*)s1; g.M[0] = N1;
        g.A0[1] = aggb; g.A1[1] = h0;
        g.W0[1] = Wph + (size_t)2 * DD * DD;
        g.W1[1] = Wph + (size_t)3 * DD * DD;
        g.bias[1] = bp + 1 * DD; g.C[1] = nullptr; g.Split[1] = (uint32_t*)s0; g.M[1] = N0;
        int mmax = (N0 > N1 ? N0 : N1);
        dim3 gr(4, (mmax + 127) / 128, 2);
        gemm_fp16_k<<<gr, 256, GEMM_SMEM>>>(g);
    }

    // ---- layer 2: fused dual gather over s0/s1 ----
    {
        int totw = N1 + N0;
        gather2h_k<<<(totw + 7) / 8, 256>>>(s0, csr01, rs01, N1, (uint4*)agga,
                                            s1, csr10, rs10, N0, (uint4*)aggb);
    }
    // ---- layer 2 fused GEMM pair -> fp32 outputs ----
    {
        float* out0 = (float*)d_out;
        float* out1 = out0 + (size_t)N0 * DD;
        G2 g;
        g.A0[0] = agga; g.A1[0] = s1;
        g.W0[0] = Wph + (size_t)4 * DD * DD;
        g.W1[0] = Wph + (size_t)5 * DD * DD;
        g.bias[0] = bp + 2 * DD; g.C[0] = out1; g.Split[0] = nullptr; g.M[0] = N1;
        g.A0[1] = aggb; g.A1[1] = s0;
        g.W0[1] = Wph + (size_t)6 * DD * DD;
        g.W1[1] = Wph + (size_t)7 * DD * DD;
        g.bias[1] = bp + 3 * DD; g.C[1] = out0; g.Split[1] = nullptr; g.M[1] = N0;
        int mmax = (N0 > N1 ? N0 : N1);
        dim3 gr(4, (mmax + 127) / 128, 2);
        gemm_fp16_k<<<gr, 256, GEMM_SMEM>>>(g);
    }
}